// round 7
// baseline (speedup 1.0000x reference)
#include <cuda_runtime.h>
#include <cuda_fp16.h>
#include <cstdint>

#define NQ 2048
#define NB 40000
#define NK 2048
#define ND 512
#define RT 64

// ======================= device scratch (no allocation allowed) ==========
__device__ float g_c2[NK];
__device__ float g_x2[NB];
__device__ float g_bestd[NB];
__device__ int g_idx[NB];
__device__ __align__(16) float g_sall[(size_t)NQ * NK];   // 16 MB
__device__ int g_nflag;
__device__ int g_flag[16384];
__device__ __half g_eh0[(size_t)NB * ND];
__device__ __half g_eh1[(size_t)NB * ND];
__device__ __half g_ch0[(size_t)NK * ND];
__device__ __half g_ch1[(size_t)NK * ND];
__device__ __half g_qh0[(size_t)NQ * ND];
__device__ __half g_qh1[(size_t)NQ * ND];

// ======================= helpers =========================================
__device__ __forceinline__ uint32_t smem_to_u32(const void* p) {
    uint32_t a;
    asm("{ .reg .u64 t; cvta.to.shared.u64 t, %1; cvt.u32.u64 %0, t; }" : "=r"(a) : "l"(p));
    return a;
}
__device__ __forceinline__ void ldsm4(uint32_t* d, uint32_t addr) {
    asm volatile("ldmatrix.sync.aligned.m8n8.x4.shared.b16 {%0,%1,%2,%3}, [%4];"
        : "=r"(d[0]), "=r"(d[1]), "=r"(d[2]), "=r"(d[3]) : "r"(addr));
}
__device__ __forceinline__ void mma16816(float* c, const uint32_t* a, const uint32_t* b) {
    asm volatile("mma.sync.aligned.m16n8k16.row.col.f32.f16.f16.f32 "
        "{%0,%1,%2,%3}, {%4,%5,%6,%7}, {%8,%9}, {%0,%1,%2,%3};"
        : "+f"(c[0]), "+f"(c[1]), "+f"(c[2]), "+f"(c[3])
        : "r"(a[0]), "r"(a[1]), "r"(a[2]), "r"(a[3]), "r"(b[0]), "r"(b[1]));
}
__device__ __forceinline__ void cpa16(uint32_t dst, const void* src) {
    asm volatile("cp.async.cg.shared.global [%0], [%1], 16;" :: "r"(dst), "l"(src));
}
#define CPA_COMMIT() asm volatile("cp.async.commit_group;" ::: "memory")
#define CPA_WAIT2()  asm volatile("cp.async.wait_group 2;" ::: "memory")
#define CPA_WAIT1()  asm volatile("cp.async.wait_group 1;" ::: "memory")
#define CPA_WAIT0()  asm volatile("cp.async.wait_group 0;" ::: "memory")

// ======================= fused row split + norms =========================
__global__ void k_splitrow(const float* __restrict__ src, int nrows, int which) {
    int gw = (blockIdx.x * 256 + threadIdx.x) >> 5;
    int lane = threadIdx.x & 31;
    if (which == 1 && gw == 0 && lane == 0) g_nflag = 0;
    if (gw >= nrows) return;
    const float* row = src + (size_t)gw * ND;
    __half *h0, *h1;
    if (which == 0) { h0 = g_eh0; h1 = g_eh1; }
    else if (which == 1) { h0 = g_ch0; h1 = g_ch1; }
    else { h0 = g_qh0; h1 = g_qh1; }
    float s = 0.f;
    #pragma unroll
    for (int j = 0; j < 4; j++) {
        int d = lane * 4 + j * 128;
        float4 v = *(const float4*)(row + d);
        __half a0 = __float2half_rn(v.x), a1 = __float2half_rn(v.y);
        __half a2 = __float2half_rn(v.z), a3 = __float2half_rn(v.w);
        __half b0 = __float2half_rn(v.x - __half2float(a0));
        __half b1 = __float2half_rn(v.y - __half2float(a1));
        __half b2 = __float2half_rn(v.z - __half2float(a2));
        __half b3 = __float2half_rn(v.w - __half2float(a3));
        __half2* p0 = (__half2*)(h0 + (size_t)gw * ND + d);
        __half2* p1 = (__half2*)(h1 + (size_t)gw * ND + d);
        p0[0] = __halves2half2(a0, a1); p0[1] = __halves2half2(a2, a3);
        p1[0] = __halves2half2(b0, b1); p1[1] = __halves2half2(b2, b3);
        s += v.x * v.x + v.y * v.y + v.z * v.z + v.w * v.w;
    }
    #pragma unroll
    for (int o = 16; o > 0; o >>= 1) s += __shfl_xor_sync(0xffffffffu, s, o);
    if (lane == 0) {
        if (which == 0) g_x2[gw] = s;
        else if (which == 1) g_c2[gw] = s;
    }
}

// ======================= HMMA distance + fused argmin ====================
// 625 CTAs x 64 rows, 256 threads (2m x 4n warps), 3-stage cp.async, 2 CTAs/SM.
// 2-product emulation: (A0+A1)*B0 = x . fp16(c); exact repair handles the
// dropped x.(c-fp16(c)) term (sigma ~0.02 << flag threshold 0.25).
// Stage: A0 8K | A1 8K | B0 16K = 32KB.
#define STG_D 32768
#define DIST_SMEM (3 * STG_D)

__device__ __forceinline__ void issue_d(uint32_t base, size_t arow, size_t brow, int koff) {
    const int tid = threadIdx.x;
    #pragma unroll
    for (int i = 0; i < 2; i++) {
        int idx = tid + i * 256;
        int r = idx >> 3, c16 = idx & 7;
        uint32_t soff = (uint32_t)(r * 128 + ((c16 * 16) ^ ((r & 7) * 16)));
        size_t off = arow + (size_t)r * ND + koff + c16 * 8;
        cpa16(base + soff,         g_eh0 + off);
        cpa16(base + 8192u + soff, g_eh1 + off);
    }
    #pragma unroll
    for (int i = 0; i < 4; i++) {
        int idx = tid + i * 256;
        int r = idx >> 3, c16 = idx & 7;
        uint32_t soff = (uint32_t)(r * 128 + ((c16 * 16) ^ ((r & 7) * 16)));
        cpa16(base + 16384u + soff, g_ch0 + brow + (size_t)r * ND + koff + c16 * 8);
    }
}

__global__ __launch_bounds__(256, 2)
void k_dist(float* __restrict__ out) {
    extern __shared__ char smem[];
    const uint32_t sb = smem_to_u32(smem);
    const int tid = threadIdx.x;
    const int wid = tid >> 5, lane = tid & 31;
    const int warp_m = wid >> 2, warp_n = wid & 3;
    const int row0 = blockIdx.x * RT;
    const size_t arow = (size_t)row0 * ND;

    const int a_row = lane & 15;
    const int a_c0 = (lane >> 4) * 16;
    const int a_xr = (a_row & 7) * 16;
    const int b_row = (lane & 7) + ((lane >> 4) << 3);
    const int b_c0 = ((lane >> 3) & 1) * 16;
    const int b_xr = (b_row & 7) * 16;
    uint32_t a_off[2], b_off[2];
    #pragma unroll
    for (int am = 0; am < 2; am++)
        a_off[am] = (uint32_t)((warp_m * 32 + am * 16 + a_row) * 128);
    #pragma unroll
    for (int bp = 0; bp < 2; bp++)
        b_off[bp] = 16384u + (uint32_t)((warp_n * 32 + bp * 16 + b_row) * 128);

    float best[4], best2[4]; int bidx[4];
    #pragma unroll
    for (int k = 0; k < 4; k++) { best[k] = 3.4e38f; best2[k] = 3.4e38f; bidx[k] = 0; }
    float acc[2][4][4];

    issue_d(sb, arow, 0, 0); CPA_COMMIT();
    issue_d(sb + STG_D, arow, 0, 64); CPA_COMMIT();

    for (int s = 0; s < 128; s++) {
        const int nt = s >> 3, kc = s & 7;
        if (s < 126) {
            const int s2 = s + 2;
            issue_d(sb + (uint32_t)(s2 % 3) * STG_D,
                    arow, (size_t)((s2 >> 3) * 128) * ND, (s2 & 7) * 64);
            CPA_COMMIT();
            CPA_WAIT2();
        } else if (s == 126) { CPA_WAIT1(); }
        else { CPA_WAIT0(); }
        __syncthreads();
        if (kc == 0) {
            #pragma unroll
            for (int am = 0; am < 2; am++)
                #pragma unroll
                for (int an = 0; an < 4; an++)
                    #pragma unroll
                    for (int r = 0; r < 4; r++) acc[am][an][r] = 0.f;
        }
        const uint32_t base = sb + (uint32_t)(s % 3) * STG_D;
        #pragma unroll
        for (int kb = 0; kb < 4; kb++) {
            const uint32_t ca = (uint32_t)((a_c0 + kb * 32) ^ a_xr);
            const uint32_t cbo = (uint32_t)((b_c0 + kb * 32) ^ b_xr);
            uint32_t af[2][4], bf[4][2];
            #pragma unroll
            for (int bp = 0; bp < 2; bp++) {
                uint32_t t[4];
                ldsm4(t, base + b_off[bp] + cbo);
                bf[bp * 2][0] = t[0]; bf[bp * 2][1] = t[1];
                bf[bp * 2 + 1][0] = t[2]; bf[bp * 2 + 1][1] = t[3];
            }
            #pragma unroll
            for (int am = 0; am < 2; am++) ldsm4(af[am], base + a_off[am] + ca);
            #pragma unroll
            for (int am = 0; am < 2; am++)
                #pragma unroll
                for (int an = 0; an < 4; an++) mma16816(acc[am][an], af[am], bf[an]);
            #pragma unroll
            for (int am = 0; am < 2; am++) ldsm4(af[am], base + a_off[am] + 8192u + ca);
            #pragma unroll
            for (int am = 0; am < 2; am++)
                #pragma unroll
                for (int an = 0; an < 4; an++) mma16816(acc[am][an], af[am], bf[an]);
        }
        if (kc == 7) {
            #pragma unroll
            for (int am = 0; am < 2; am++) {
                #pragma unroll
                for (int an = 0; an < 4; an++) {
                    int cl = warp_n * 32 + an * 8 + (lane & 3) * 2;
                    float c2a = __ldg(&g_c2[nt * 128 + cl]);
                    float c2b = __ldg(&g_c2[nt * 128 + cl + 1]);
                    int gc = nt * 128 + cl;
                    #pragma unroll
                    for (int h = 0; h < 2; h++) {
                        int k = am * 2 + h;
                        float d0 = c2a - 2.f * acc[am][an][h * 2 + 0];
                        float d1 = c2b - 2.f * acc[am][an][h * 2 + 1];
                        if (d0 < best[k]) { best2[k] = best[k]; best[k] = d0; bidx[k] = gc; }
                        else if (d0 < best2[k]) best2[k] = d0;
                        if (d1 < best[k]) { best2[k] = best[k]; best[k] = d1; bidx[k] = gc + 1; }
                        else if (d1 < best2[k]) best2[k] = d1;
                    }
                }
            }
        }
        __syncthreads();
    }

    // ---- final reduce: quad lanes -> smem -> per-row ----
    float* sred1 = (float*)smem;
    float* sred2 = (float*)(smem + 1024);
    int*   sredi = (int*)(smem + 2048);
    #pragma unroll
    for (int k = 0; k < 4; k++) {
        float b1 = best[k], b2 = best2[k]; int ix = bidx[k];
        #pragma unroll
        for (int s = 1; s < 4; s <<= 1) {
            float o1 = __shfl_xor_sync(0xffffffffu, b1, s);
            float o2 = __shfl_xor_sync(0xffffffffu, b2, s);
            int oi = __shfl_xor_sync(0xffffffffu, ix, s);
            if (o1 < b1) { b2 = fminf(b1, o2); b1 = o1; ix = oi; }
            else b2 = fminf(b2, o1);
        }
        if ((lane & 3) == 0) {
            int rl = warp_m * 32 + (k >> 1) * 16 + (k & 1) * 8 + (lane >> 2);
            sred1[rl * 4 + warp_n] = b1;
            sred2[rl * 4 + warp_n] = b2;
            sredi[rl * 4 + warp_n] = ix;
        }
    }
    __syncthreads();
    if (tid < RT) {
        float b1 = sred1[tid * 4], b2 = sred2[tid * 4];
        int ix = sredi[tid * 4];
        #pragma unroll
        for (int w = 1; w < 4; w++) {
            float o1 = sred1[tid * 4 + w], o2 = sred2[tid * 4 + w];
            int oi = sredi[tid * 4 + w];
            if (o1 < b1) { b2 = fminf(b1, o2); b1 = o1; ix = oi; }
            else b2 = fminf(b2, o1);
        }
        int row = row0 + tid;
        g_idx[row] = ix;
        g_bestd[row] = b1;
        out[(size_t)NQ * NB + 1 + row] = (float)ix;
        if (b2 - b1 < 0.25f) {
            int s = atomicAdd(&g_nflag, 1);
            if (s < 16384) g_flag[s] = row;
        }
    }
}

// ======================= exact fp32 repair for near-ties =================
__global__ __launch_bounds__(256)
void k_repair(const float* __restrict__ ent, const float* __restrict__ cb,
              float* __restrict__ out) {
    __shared__ float sx[ND];
    __shared__ unsigned long long red[256];
    const int tid = threadIdx.x;
    int n = g_nflag;
    if (n > 16384) n = 16384;
    for (int f = blockIdx.x; f < n; f += gridDim.x) {
        const int b = g_flag[f];
        sx[tid] = ent[(size_t)b * ND + tid];
        sx[tid + 256] = ent[(size_t)b * ND + tid + 256];
        __syncthreads();
        float best = 3.4e38f;
        int bj = 0;
        const int j0 = tid * 8;
        for (int jj = 0; jj < 8; jj++) {
            const int j = j0 + jj;
            const float* c = cb + (size_t)j * ND;
            float dot = 0.f;
            #pragma unroll 8
            for (int d = 0; d < ND; d++) dot = fmaf(sx[d], c[d], dot);
            float d2 = g_c2[j] - 2.0f * dot;
            if (d2 < best) { best = d2; bj = j; }
        }
        unsigned int kb = __float_as_uint(best);
        kb = (kb & 0x80000000u) ? ~kb : (kb | 0x80000000u);
        red[tid] = ((unsigned long long)kb << 32) | (unsigned int)bj;
        __syncthreads();
        for (int o = 128; o > 0; o >>= 1) {
            if (tid < o) { unsigned long long v = red[tid + o]; if (v < red[tid]) red[tid] = v; }
            __syncthreads();
        }
        if (tid == 0) {
            unsigned long long w = red[0];
            int j = (int)(unsigned int)(w & 0xFFFFFFFFull);
            unsigned int kk = (unsigned int)(w >> 32);
            unsigned int fb = (kk & 0x80000000u) ? (kk & 0x7FFFFFFFu) : ~kk;
            g_idx[b] = j;
            g_bestd[b] = __uint_as_float(fb);
            out[(size_t)NQ * NB + 1 + b] = (float)j;
        }
        __syncthreads();
    }
}

// ======================= S_all = query @ codebook^T (3-product HMMA) =====
#define STG_S 49152
#define SALL_SMEM (2 * STG_S)

__device__ __forceinline__ void issue_s(uint32_t base, size_t arow, size_t brow, int koff) {
    const int tid = threadIdx.x;
    #pragma unroll
    for (int i = 0; i < 2; i++) {
        int idx = tid + i * 256;
        int r = idx >> 3, c16 = idx & 7;
        uint32_t soff = (uint32_t)(r * 128 + ((c16 * 16) ^ ((r & 7) * 16)));
        size_t off = arow + (size_t)r * ND + koff + c16 * 8;
        cpa16(base + soff,         g_qh0 + off);
        cpa16(base + 8192u + soff, g_qh1 + off);
    }
    #pragma unroll
    for (int i = 0; i < 4; i++) {
        int idx = tid + i * 256;
        int r = idx >> 3, c16 = idx & 7;
        uint32_t soff = (uint32_t)(r * 128 + ((c16 * 16) ^ ((r & 7) * 16)));
        size_t off = brow + (size_t)r * ND + koff + c16 * 8;
        cpa16(base + 16384u + soff, g_ch0 + off);
        cpa16(base + 32768u + soff, g_ch1 + off);
    }
}

__global__ __launch_bounds__(256, 2)
void k_sall() {
    extern __shared__ char smem[];
    const uint32_t sb = smem_to_u32(smem);
    const int tid = threadIdx.x;
    const int wid = tid >> 5, lane = tid & 31;
    const int warp_m = wid >> 2, warp_n = wid & 3;
    const int col0 = blockIdx.x * 128;
    const int row0 = blockIdx.y * RT;
    const size_t arow = (size_t)row0 * ND;
    const size_t brow = (size_t)col0 * ND;

    const int a_row = lane & 15;
    const int a_c0 = (lane >> 4) * 16;
    const int a_xr = (a_row & 7) * 16;
    const int b_row = (lane & 7) + ((lane >> 4) << 3);
    const int b_c0 = ((lane >> 3) & 1) * 16;
    const int b_xr = (b_row & 7) * 16;
    uint32_t a_off[2], b_off[2];
    #pragma unroll
    for (int am = 0; am < 2; am++)
        a_off[am] = (uint32_t)((warp_m * 32 + am * 16 + a_row) * 128);
    #pragma unroll
    for (int bp = 0; bp < 2; bp++)
        b_off[bp] = 16384u + (uint32_t)((warp_n * 32 + bp * 16 + b_row) * 128);

    float acc[2][4][4];
    #pragma unroll
    for (int am = 0; am < 2; am++)
        #pragma unroll
        for (int an = 0; an < 4; an++)
            #pragma unroll
            for (int r = 0; r < 4; r++) acc[am][an][r] = 0.f;

    issue_s(sb, arow, brow, 0); CPA_COMMIT();

    for (int s = 0; s < 8; s++) {
        if (s < 7) {
            issue_s(sb + (uint32_t)((s + 1) & 1) * STG_S, arow, brow, (s + 1) * 64);
            CPA_COMMIT();
            CPA_WAIT1();
        } else {
            CPA_WAIT0();
        }
        __syncthreads();
        const uint32_t base = sb + (uint32_t)(s & 1) * STG_S;
        #pragma unroll
        for (int kb = 0; kb < 4; kb++) {
            const uint32_t ca = (uint32_t)((a_c0 + kb * 32) ^ a_xr);
            const uint32_t cbo = (uint32_t)((b_c0 + kb * 32) ^ b_xr);
            uint32_t af[2][4], bf[4][2], bg[4][2];
            #pragma unroll
            for (int bp = 0; bp < 2; bp++) {
                uint32_t t[4];
                ldsm4(t, base + b_off[bp] + cbo);
                bf[bp * 2][0] = t[0]; bf[bp * 2][1] = t[1];
                bf[bp * 2 + 1][0] = t[2]; bf[bp * 2 + 1][1] = t[3];
            }
            #pragma unroll
            for (int bp = 0; bp < 2; bp++) {
                uint32_t t[4];
                ldsm4(t, base + b_off[bp] + 16384u + cbo);
                bg[bp * 2][0] = t[0]; bg[bp * 2][1] = t[1];
                bg[bp * 2 + 1][0] = t[2]; bg[bp * 2 + 1][1] = t[3];
            }
            #pragma unroll
            for (int am = 0; am < 2; am++) ldsm4(af[am], base + a_off[am] + ca);
            #pragma unroll
            for (int am = 0; am < 2; am++)
                #pragma unroll
                for (int an = 0; an < 4; an++) mma16816(acc[am][an], af[am], bf[an]);
            #pragma unroll
            for (int am = 0; am < 2; am++)
                #pragma unroll
                for (int an = 0; an < 4; an++) mma16816(acc[am][an], af[am], bg[an]);
            #pragma unroll
            for (int am = 0; am < 2; am++) ldsm4(af[am], base + a_off[am] + 8192u + ca);
            #pragma unroll
            for (int am = 0; am < 2; am++)
                #pragma unroll
                for (int an = 0; an < 4; an++) mma16816(acc[am][an], af[am], bf[an]);
        }
        __syncthreads();
    }

    #pragma unroll
    for (int am = 0; am < 2; am++)
        #pragma unroll
        for (int h = 0; h < 2; h++) {
            int r = row0 + warp_m * 32 + am * 16 + h * 8 + (lane >> 2);
            #pragma unroll
            for (int an = 0; an < 4; an++) {
                int c = col0 + warp_n * 32 + an * 8 + (lane & 3) * 2;
                *(float2*)(g_sall + (size_t)r * NK + c) =
                    make_float2(acc[am][an][h * 2], acc[am][an][h * 2 + 1]);
            }
        }
}

// ======================= vq_loss: mean(x2 + bestd) * 1.25 ================
__global__ void k_loss_final(float* __restrict__ out) {
    __shared__ double sred[256];
    const int tid = threadIdx.x;
    double s = 0.0;
    for (int b = tid; b < NB; b += 256) s += (double)g_x2[b] + (double)g_bestd[b];
    sred[tid] = s;
    __syncthreads();
    for (int o = 128; o > 0; o >>= 1) {
        if (tid < o) sred[tid] += sred[tid + o];
        __syncthreads();
    }
    if (tid == 0) out[(size_t)NQ * NB] = (float)(1.25 * sred[0] / ((double)NB * (double)ND));
}

// ======================= score gather ====================================
#define QCH 8
#define GATHER_SMEM (QCH * NK * 4)
__global__ __launch_bounds__(512)
void k_gather(float* __restrict__ out) {
    extern __shared__ float srow[];   // [QCH][NK]
    const int tid = threadIdx.x;
    const int q0 = blockIdx.x * QCH;
    for (int i = tid; i < QCH * NK / 4; i += 512)
        ((float4*)srow)[i] = ((const float4*)(g_sall + (size_t)q0 * NK))[i];
    __syncthreads();
    for (int c = 0; c < 10; c++) {
        int b = c * 4096 + tid * 8;
        if (b >= NB) continue;
        int idx8[8];
        #pragma unroll
        for (int t = 0; t < 8; t++) idx8[t] = g_idx[b + t];
        #pragma unroll
        for (int q = 0; q < QCH; q++) {
            const float* r = srow + q * NK;
            float4 v0 = make_float4(r[idx8[0]], r[idx8[1]], r[idx8[2]], r[idx8[3]]);
            float4 v1 = make_float4(r[idx8[4]], r[idx8[5]], r[idx8[6]], r[idx8[7]]);
            float* p = out + (size_t)(q0 + q) * NB + b;
            __stcs((float4*)p, v0);
            __stcs((float4*)(p + 4), v1);
        }
    }
}

// ======================= launch ==========================================
extern "C" void kernel_launch(void* const* d_in, const int* in_sizes, int n_in,
                              void* d_out, int out_size) {
    const float* qry = (const float*)d_in[0];   // (2048, 512)
    const float* ent = (const float*)d_in[1];   // (40000, 512)
    const float* cb  = (const float*)d_in[2];   // (2048, 512)
    float* out = (float*)d_out;                 // score | vq_loss | idx

    cudaFuncSetAttribute(k_dist, cudaFuncAttributeMaxDynamicSharedMemorySize, DIST_SMEM);
    cudaFuncSetAttribute(k_sall, cudaFuncAttributeMaxDynamicSharedMemorySize, SALL_SMEM);
    cudaFuncSetAttribute(k_gather, cudaFuncAttributeMaxDynamicSharedMemorySize, GATHER_SMEM);

    k_splitrow<<<(NB + 7) / 8, 256>>>(ent, NB, 0);
    k_splitrow<<<(NK + 7) / 8, 256>>>(cb, NK, 1);
    k_splitrow<<<(NQ + 7) / 8, 256>>>(qry, NQ, 2);
    k_dist<<<625, 256, DIST_SMEM>>>(out);
    k_repair<<<512, 256>>>(ent, cb, out);
    k_sall<<<dim3(16, 32), 256, SALL_SMEM>>>();
    k_loss_final<<<1, 256>>>(out);
    k_gather<<<256, 512, GATHER_SMEM>>>(out);
}

// round 9
// speedup vs baseline: 4.7179x; 4.7179x over previous
#include <cuda_runtime.h>
#include <cuda_fp16.h>
#include <cstdint>

#define NQ 2048
#define NB 40000
#define NK 2048
#define ND 512
#define RT 64
#define MAXFLAG 16384

// ======================= device scratch (no allocation allowed) ==========
__device__ float g_c2[NK];
__device__ float g_x2[NB];
__device__ float g_bestd[NB];
__device__ int g_idx[NB];
__device__ __align__(16) float g_sall[(size_t)NQ * NK];   // 16 MB
__device__ int g_nflag;
__device__ int g_flag[MAXFLAG];
__device__ unsigned long long g_min[MAXFLAG];
__device__ __half g_eh0[(size_t)NB * ND];
__device__ __half g_eh1[(size_t)NB * ND];
__device__ __half g_ch0[(size_t)NK * ND];
__device__ __half g_ch1[(size_t)NK * ND];
__device__ __half g_qh0[(size_t)NQ * ND];
__device__ __half g_qh1[(size_t)NQ * ND];

// ======================= helpers =========================================
__device__ __forceinline__ uint32_t smem_to_u32(const void* p) {
    uint32_t a;
    asm("{ .reg .u64 t; cvta.to.shared.u64 t, %1; cvt.u32.u64 %0, t; }" : "=r"(a) : "l"(p));
    return a;
}
__device__ __forceinline__ void ldsm4(uint32_t* d, uint32_t addr) {
    asm volatile("ldmatrix.sync.aligned.m8n8.x4.shared.b16 {%0,%1,%2,%3}, [%4];"
        : "=r"(d[0]), "=r"(d[1]), "=r"(d[2]), "=r"(d[3]) : "r"(addr));
}
__device__ __forceinline__ void mma16816(float* c, const uint32_t* a, const uint32_t* b) {
    asm volatile("mma.sync.aligned.m16n8k16.row.col.f32.f16.f16.f32 "
        "{%0,%1,%2,%3}, {%4,%5,%6,%7}, {%8,%9}, {%0,%1,%2,%3};"
        : "+f"(c[0]), "+f"(c[1]), "+f"(c[2]), "+f"(c[3])
        : "r"(a[0]), "r"(a[1]), "r"(a[2]), "r"(a[3]), "r"(b[0]), "r"(b[1]));
}
__device__ __forceinline__ void cpa16(uint32_t dst, const void* src) {
    asm volatile("cp.async.cg.shared.global [%0], [%1], 16;" :: "r"(dst), "l"(src));
}
#define CPA_COMMIT() asm volatile("cp.async.commit_group;" ::: "memory")
#define CPA_WAIT2()  asm volatile("cp.async.wait_group 2;" ::: "memory")
#define CPA_WAIT1()  asm volatile("cp.async.wait_group 1;" ::: "memory")
#define CPA_WAIT0()  asm volatile("cp.async.wait_group 0;" ::: "memory")

// ======================= fused row split + norms =========================
__global__ void k_splitrow(const float* __restrict__ src, int nrows, int which) {
    int gw = (blockIdx.x * 256 + threadIdx.x) >> 5;
    int lane = threadIdx.x & 31;
    if (which == 1 && gw == 0 && lane == 0) g_nflag = 0;
    if (gw >= nrows) return;
    const float* row = src + (size_t)gw * ND;
    __half *h0, *h1;
    if (which == 0) { h0 = g_eh0; h1 = g_eh1; }
    else if (which == 1) { h0 = g_ch0; h1 = g_ch1; }
    else { h0 = g_qh0; h1 = g_qh1; }
    float s = 0.f;
    #pragma unroll
    for (int j = 0; j < 4; j++) {
        int d = lane * 4 + j * 128;
        float4 v = *(const float4*)(row + d);
        __half a0 = __float2half_rn(v.x), a1 = __float2half_rn(v.y);
        __half a2 = __float2half_rn(v.z), a3 = __float2half_rn(v.w);
        __half b0 = __float2half_rn(v.x - __half2float(a0));
        __half b1 = __float2half_rn(v.y - __half2float(a1));
        __half b2 = __float2half_rn(v.z - __half2float(a2));
        __half b3 = __float2half_rn(v.w - __half2float(a3));
        __half2* p0 = (__half2*)(h0 + (size_t)gw * ND + d);
        __half2* p1 = (__half2*)(h1 + (size_t)gw * ND + d);
        p0[0] = __halves2half2(a0, a1); p0[1] = __halves2half2(a2, a3);
        p1[0] = __halves2half2(b0, b1); p1[1] = __halves2half2(b2, b3);
        s += v.x * v.x + v.y * v.y + v.z * v.z + v.w * v.w;
    }
    #pragma unroll
    for (int o = 16; o > 0; o >>= 1) s += __shfl_xor_sync(0xffffffffu, s, o);
    if (lane == 0) {
        if (which == 0) g_x2[gw] = s;
        else if (which == 1) g_c2[gw] = s;
    }
}

__global__ void k_flaginit() {
    g_min[blockIdx.x * 256 + threadIdx.x] = 0xFFFFFFFFFFFFFFFFull;
}

// ======================= HMMA distance + fused argmin ====================
// 625 CTAs x 64 rows, 256 threads (2m x 4n warps), 3-stage cp.async, 2 CTAs/SM.
// 2-product emulation: (A0+A1)*B0 = x . fp16(c); GEMM repair fixes rows with
// margin < 0.25 (dropped-term sigma ~0.013).
#define STG_D 32768
#define DIST_SMEM (3 * STG_D)

__device__ __forceinline__ void issue_d(uint32_t base, size_t arow, size_t brow, int koff) {
    const int tid = threadIdx.x;
    #pragma unroll
    for (int i = 0; i < 2; i++) {
        int idx = tid + i * 256;
        int r = idx >> 3, c16 = idx & 7;
        uint32_t soff = (uint32_t)(r * 128 + ((c16 * 16) ^ ((r & 7) * 16)));
        size_t off = arow + (size_t)r * ND + koff + c16 * 8;
        cpa16(base + soff,         g_eh0 + off);
        cpa16(base + 8192u + soff, g_eh1 + off);
    }
    #pragma unroll
    for (int i = 0; i < 4; i++) {
        int idx = tid + i * 256;
        int r = idx >> 3, c16 = idx & 7;
        uint32_t soff = (uint32_t)(r * 128 + ((c16 * 16) ^ ((r & 7) * 16)));
        cpa16(base + 16384u + soff, g_ch0 + brow + (size_t)r * ND + koff + c16 * 8);
    }
}

__global__ __launch_bounds__(256, 2)
void k_dist(float* __restrict__ out) {
    extern __shared__ char smem[];
    const uint32_t sb = smem_to_u32(smem);
    const int tid = threadIdx.x;
    const int wid = tid >> 5, lane = tid & 31;
    const int warp_m = wid >> 2, warp_n = wid & 3;
    const int row0 = blockIdx.x * RT;
    const size_t arow = (size_t)row0 * ND;

    const int a_row = lane & 15;
    const int a_c0 = (lane >> 4) * 16;
    const int a_xr = (a_row & 7) * 16;
    const int b_row = (lane & 7) + ((lane >> 4) << 3);
    const int b_c0 = ((lane >> 3) & 1) * 16;
    const int b_xr = (b_row & 7) * 16;
    uint32_t a_off[2], b_off[2];
    #pragma unroll
    for (int am = 0; am < 2; am++)
        a_off[am] = (uint32_t)((warp_m * 32 + am * 16 + a_row) * 128);
    #pragma unroll
    for (int bp = 0; bp < 2; bp++)
        b_off[bp] = 16384u + (uint32_t)((warp_n * 32 + bp * 16 + b_row) * 128);

    float best[4], best2[4]; int bidx[4];
    #pragma unroll
    for (int k = 0; k < 4; k++) { best[k] = 3.4e38f; best2[k] = 3.4e38f; bidx[k] = 0; }
    float acc[2][4][4];

    issue_d(sb, arow, 0, 0); CPA_COMMIT();
    issue_d(sb + STG_D, arow, 0, 64); CPA_COMMIT();

    for (int s = 0; s < 128; s++) {
        const int nt = s >> 3, kc = s & 7;
        if (s < 126) {
            const int s2 = s + 2;
            issue_d(sb + (uint32_t)(s2 % 3) * STG_D,
                    arow, (size_t)((s2 >> 3) * 128) * ND, (s2 & 7) * 64);
            CPA_COMMIT();
            CPA_WAIT2();
        } else if (s == 126) { CPA_WAIT1(); }
        else { CPA_WAIT0(); }
        __syncthreads();
        if (kc == 0) {
            #pragma unroll
            for (int am = 0; am < 2; am++)
                #pragma unroll
                for (int an = 0; an < 4; an++)
                    #pragma unroll
                    for (int r = 0; r < 4; r++) acc[am][an][r] = 0.f;
        }
        const uint32_t base = sb + (uint32_t)(s % 3) * STG_D;
        #pragma unroll
        for (int kb = 0; kb < 4; kb++) {
            const uint32_t ca = (uint32_t)((a_c0 + kb * 32) ^ a_xr);
            const uint32_t cbo = (uint32_t)((b_c0 + kb * 32) ^ b_xr);
            uint32_t af[2][4], bf[4][2];
            #pragma unroll
            for (int bp = 0; bp < 2; bp++) {
                uint32_t t[4];
                ldsm4(t, base + b_off[bp] + cbo);
                bf[bp * 2][0] = t[0]; bf[bp * 2][1] = t[1];
                bf[bp * 2 + 1][0] = t[2]; bf[bp * 2 + 1][1] = t[3];
            }
            #pragma unroll
            for (int am = 0; am < 2; am++) ldsm4(af[am], base + a_off[am] + ca);
            #pragma unroll
            for (int am = 0; am < 2; am++)
                #pragma unroll
                for (int an = 0; an < 4; an++) mma16816(acc[am][an], af[am], bf[an]);
            #pragma unroll
            for (int am = 0; am < 2; am++) ldsm4(af[am], base + a_off[am] + 8192u + ca);
            #pragma unroll
            for (int am = 0; am < 2; am++)
                #pragma unroll
                for (int an = 0; an < 4; an++) mma16816(acc[am][an], af[am], bf[an]);
        }
        if (kc == 7) {
            #pragma unroll
            for (int am = 0; am < 2; am++) {
                #pragma unroll
                for (int an = 0; an < 4; an++) {
                    int cl = warp_n * 32 + an * 8 + (lane & 3) * 2;
                    float c2a = __ldg(&g_c2[nt * 128 + cl]);
                    float c2b = __ldg(&g_c2[nt * 128 + cl + 1]);
                    int gc = nt * 128 + cl;
                    #pragma unroll
                    for (int h = 0; h < 2; h++) {
                        int k = am * 2 + h;
                        float d0 = c2a - 2.f * acc[am][an][h * 2 + 0];
                        float d1 = c2b - 2.f * acc[am][an][h * 2 + 1];
                        if (d0 < best[k]) { best2[k] = best[k]; best[k] = d0; bidx[k] = gc; }
                        else if (d0 < best2[k]) best2[k] = d0;
                        if (d1 < best[k]) { best2[k] = best[k]; best[k] = d1; bidx[k] = gc + 1; }
                        else if (d1 < best2[k]) best2[k] = d1;
                    }
                }
            }
        }
        __syncthreads();
    }

    // ---- final reduce: quad lanes -> smem -> per-row ----
    float* sred1 = (float*)smem;
    float* sred2 = (float*)(smem + 1024);
    int*   sredi = (int*)(smem + 2048);
    #pragma unroll
    for (int k = 0; k < 4; k++) {
        float b1 = best[k], b2 = best2[k]; int ix = bidx[k];
        #pragma unroll
        for (int s = 1; s < 4; s <<= 1) {
            float o1 = __shfl_xor_sync(0xffffffffu, b1, s);
            float o2 = __shfl_xor_sync(0xffffffffu, b2, s);
            int oi = __shfl_xor_sync(0xffffffffu, ix, s);
            if (o1 < b1) { b2 = fminf(b1, o2); b1 = o1; ix = oi; }
            else b2 = fminf(b2, o1);
        }
        if ((lane & 3) == 0) {
            int rl = warp_m * 32 + (k >> 1) * 16 + (k & 1) * 8 + (lane >> 2);
            sred1[rl * 4 + warp_n] = b1;
            sred2[rl * 4 + warp_n] = b2;
            sredi[rl * 4 + warp_n] = ix;
        }
    }
    __syncthreads();
    if (tid < RT) {
        float b1 = sred1[tid * 4], b2 = sred2[tid * 4];
        int ix = sredi[tid * 4];
        #pragma unroll
        for (int w = 1; w < 4; w++) {
            float o1 = sred1[tid * 4 + w], o2 = sred2[tid * 4 + w];
            int oi = sredi[tid * 4 + w];
            if (o1 < b1) { b2 = fminf(b1, o2); b1 = o1; ix = oi; }
            else b2 = fminf(b2, o1);
        }
        int row = row0 + tid;
        g_idx[row] = ix;
        g_bestd[row] = b1;
        out[(size_t)NQ * NB + 1 + row] = (float)ix;
        if (b2 - b1 < 0.25f) {
            int s = atomicAdd(&g_nflag, 1);
            if (s < MAXFLAG) g_flag[s] = row;
        }
    }
}

// ======================= exact fp32 GEMM repair ==========================
// grid (16 col-tiles, 128 slot-tiles); 128 flagged rows x 128 codes per block.
__global__ __launch_bounds__(256)
void k_repair_gemm(const float* __restrict__ ent, const float* __restrict__ cb) {
    __shared__ float As[32][132];
    __shared__ float Bs[32][132];
    __shared__ int srow[128];
    int n = g_nflag;
    if (n > MAXFLAG) n = MAXFLAG;
    const int s0 = blockIdx.y * 128;
    if (s0 >= n) return;
    const int col0 = blockIdx.x * 128;
    const int tid = threadIdx.x;
    if (tid < 128) srow[tid] = (s0 + tid < n) ? g_flag[s0 + tid] : -1;
    __syncthreads();
    const int tcol = tid & 15;
    const int trow = tid >> 4;
    float acc[8][8] = {};

    for (int kk = 0; kk < ND; kk += 32) {
        #pragma unroll
        for (int it = 0; it < 4; it++) {
            int f4 = tid + it * 256;
            int r = f4 >> 3;
            int c = (f4 & 7) << 2;
            int er = srow[r];
            float4 v = make_float4(0.f, 0.f, 0.f, 0.f);
            if (er >= 0) v = *(const float4*)(ent + (size_t)er * ND + kk + c);
            As[c + 0][r] = v.x; As[c + 1][r] = v.y; As[c + 2][r] = v.z; As[c + 3][r] = v.w;
            float4 w = *(const float4*)(cb + (size_t)(col0 + r) * ND + kk + c);
            Bs[c + 0][r] = w.x; Bs[c + 1][r] = w.y; Bs[c + 2][r] = w.z; Bs[c + 3][r] = w.w;
        }
        __syncthreads();
        #pragma unroll
        for (int k = 0; k < 32; k++) {
            float4 a0 = *(const float4*)&As[k][trow * 8];
            float4 a1 = *(const float4*)&As[k][trow * 8 + 4];
            float4 b0 = *(const float4*)&Bs[k][tcol * 8];
            float4 b1 = *(const float4*)&Bs[k][tcol * 8 + 4];
            float a[8] = {a0.x, a0.y, a0.z, a0.w, a1.x, a1.y, a1.z, a1.w};
            float b[8] = {b0.x, b0.y, b0.z, b0.w, b1.x, b1.y, b1.z, b1.w};
            #pragma unroll
            for (int i = 0; i < 8; i++)
                #pragma unroll
                for (int j = 0; j < 8; j++)
                    acc[i][j] = fmaf(a[i], b[j], acc[i][j]);
        }
        __syncthreads();
    }

    #pragma unroll
    for (int i = 0; i < 8; i++) {
        int slot = s0 + trow * 8 + i;
        float best = 3.4e38f;
        int bj = 0;
        #pragma unroll
        for (int j = 0; j < 8; j++) {
            int gc = col0 + tcol * 8 + j;
            float d = g_c2[gc] - 2.0f * acc[i][j];
            if (d < best) { best = d; bj = gc; }
        }
        unsigned int kb = __float_as_uint(best);
        kb = (kb & 0x80000000u) ? ~kb : (kb | 0x80000000u);
        unsigned long long pack = ((unsigned long long)kb << 32) | (unsigned int)bj;
        #pragma unroll
        for (int s = 1; s < 16; s <<= 1) {
            unsigned long long o = __shfl_xor_sync(0xffffffffu, pack, s);
            pack = (o < pack) ? o : pack;
        }
        if (tcol == 0 && slot < n) atomicMin(&g_min[slot], pack);
    }
}

__global__ void k_repair_write(float* __restrict__ out) {
    int s = blockIdx.x * 256 + threadIdx.x;
    int n = g_nflag;
    if (n > MAXFLAG) n = MAXFLAG;
    if (s >= n) return;
    unsigned long long w = g_min[s];
    int j = (int)(unsigned int)(w & 0xFFFFFFFFull);
    unsigned int kb = (unsigned int)(w >> 32);
    unsigned int fb = (kb & 0x80000000u) ? (kb & 0x7FFFFFFFu) : ~kb;
    int b = g_flag[s];
    g_idx[b] = j;
    g_bestd[b] = __uint_as_float(fb);
    out[(size_t)NQ * NB + 1 + b] = (float)j;
}

// ======================= S_all = query @ codebook^T (3-product HMMA) =====
#define STG_S 49152
#define SALL_SMEM (2 * STG_S)

__device__ __forceinline__ void issue_s(uint32_t base, size_t arow, size_t brow, int koff) {
    const int tid = threadIdx.x;
    #pragma unroll
    for (int i = 0; i < 2; i++) {
        int idx = tid + i * 256;
        int r = idx >> 3, c16 = idx & 7;
        uint32_t soff = (uint32_t)(r * 128 + ((c16 * 16) ^ ((r & 7) * 16)));
        size_t off = arow + (size_t)r * ND + koff + c16 * 8;
        cpa16(base + soff,         g_qh0 + off);
        cpa16(base + 8192u + soff, g_qh1 + off);
    }
    #pragma unroll
    for (int i = 0; i < 4; i++) {
        int idx = tid + i * 256;
        int r = idx >> 3, c16 = idx & 7;
        uint32_t soff = (uint32_t)(r * 128 + ((c16 * 16) ^ ((r & 7) * 16)));
        size_t off = brow + (size_t)r * ND + koff + c16 * 8;
        cpa16(base + 16384u + soff, g_ch0 + off);
        cpa16(base + 32768u + soff, g_ch1 + off);
    }
}

__global__ __launch_bounds__(256, 2)
void k_sall() {
    extern __shared__ char smem[];
    const uint32_t sb = smem_to_u32(smem);
    const int tid = threadIdx.x;
    const int wid = tid >> 5, lane = tid & 31;
    const int warp_m = wid >> 2, warp_n = wid & 3;
    const int col0 = blockIdx.x * 128;
    const int row0 = blockIdx.y * RT;
    const size_t arow = (size_t)row0 * ND;
    const size_t brow = (size_t)col0 * ND;

    const int a_row = lane & 15;
    const int a_c0 = (lane >> 4) * 16;
    const int a_xr = (a_row & 7) * 16;
    const int b_row = (lane & 7) + ((lane >> 4) << 3);
    const int b_c0 = ((lane >> 3) & 1) * 16;
    const int b_xr = (b_row & 7) * 16;
    uint32_t a_off[2], b_off[2];
    #pragma unroll
    for (int am = 0; am < 2; am++)
        a_off[am] = (uint32_t)((warp_m * 32 + am * 16 + a_row) * 128);
    #pragma unroll
    for (int bp = 0; bp < 2; bp++)
        b_off[bp] = 16384u + (uint32_t)((warp_n * 32 + bp * 16 + b_row) * 128);

    float acc[2][4][4];
    #pragma unroll
    for (int am = 0; am < 2; am++)
        #pragma unroll
        for (int an = 0; an < 4; an++)
            #pragma unroll
            for (int r = 0; r < 4; r++) acc[am][an][r] = 0.f;

    issue_s(sb, arow, brow, 0); CPA_COMMIT();

    for (int s = 0; s < 8; s++) {
        if (s < 7) {
            issue_s(sb + (uint32_t)((s + 1) & 1) * STG_S, arow, brow, (s + 1) * 64);
            CPA_COMMIT();
            CPA_WAIT1();
        } else {
            CPA_WAIT0();
        }
        __syncthreads();
        const uint32_t base = sb + (uint32_t)(s & 1) * STG_S;
        #pragma unroll
        for (int kb = 0; kb < 4; kb++) {
            const uint32_t ca = (uint32_t)((a_c0 + kb * 32) ^ a_xr);
            const uint32_t cbo = (uint32_t)((b_c0 + kb * 32) ^ b_xr);
            uint32_t af[2][4], bf[4][2], bg[4][2];
            #pragma unroll
            for (int bp = 0; bp < 2; bp++) {
                uint32_t t[4];
                ldsm4(t, base + b_off[bp] + cbo);
                bf[bp * 2][0] = t[0]; bf[bp * 2][1] = t[1];
                bf[bp * 2 + 1][0] = t[2]; bf[bp * 2 + 1][1] = t[3];
            }
            #pragma unroll
            for (int bp = 0; bp < 2; bp++) {
                uint32_t t[4];
                ldsm4(t, base + b_off[bp] + 16384u + cbo);
                bg[bp * 2][0] = t[0]; bg[bp * 2][1] = t[1];
                bg[bp * 2 + 1][0] = t[2]; bg[bp * 2 + 1][1] = t[3];
            }
            #pragma unroll
            for (int am = 0; am < 2; am++) ldsm4(af[am], base + a_off[am] + ca);
            #pragma unroll
            for (int am = 0; am < 2; am++)
                #pragma unroll
                for (int an = 0; an < 4; an++) mma16816(acc[am][an], af[am], bf[an]);
            #pragma unroll
            for (int am = 0; am < 2; am++)
                #pragma unroll
                for (int an = 0; an < 4; an++) mma16816(acc[am][an], af[am], bg[an]);
            #pragma unroll
            for (int am = 0; am < 2; am++) ldsm4(af[am], base + a_off[am] + 8192u + ca);
            #pragma unroll
            for (int am = 0; am < 2; am++)
                #pragma unroll
                for (int an = 0; an < 4; an++) mma16816(acc[am][an], af[am], bf[an]);
        }
        __syncthreads();
    }

    #pragma unroll
    for (int am = 0; am < 2; am++)
        #pragma unroll
        for (int h = 0; h < 2; h++) {
            int r = row0 + warp_m * 32 + am * 16 + h * 8 + (lane >> 2);
            #pragma unroll
            for (int an = 0; an < 4; an++) {
                int c = col0 + warp_n * 32 + an * 8 + (lane & 3) * 2;
                *(float2*)(g_sall + (size_t)r * NK + c) =
                    make_float2(acc[am][an][h * 2], acc[am][an][h * 2 + 1]);
            }
        }
}

// ======================= vq_loss: mean(x2 + bestd) * 1.25 ================
__global__ void k_loss_final(float* __restrict__ out) {
    __shared__ double sred[256];
    const int tid = threadIdx.x;
    double s = 0.0;
    for (int b = tid; b < NB; b += 256) s += (double)g_x2[b] + (double)g_bestd[b];
    sred[tid] = s;
    __syncthreads();
    for (int o = 128; o > 0; o >>= 1) {
        if (tid < o) sred[tid] += sred[tid + o];
        __syncthreads();
    }
    if (tid == 0) out[(size_t)NQ * NB] = (float)(1.25 * sred[0] / ((double)NB * (double)ND));
}

// ======================= score gather ====================================
#define QCH 8
#define GATHER_SMEM (QCH * NK * 4)
__global__ __launch_bounds__(512)
void k_gather(float* __restrict__ out) {
    extern __shared__ float srow[];   // [QCH][NK]
    const int tid = threadIdx.x;
    const int q0 = blockIdx.x * QCH;
    for (int i = tid; i < QCH * NK / 4; i += 512)
        ((float4*)srow)[i] = ((const float4*)(g_sall + (size_t)q0 * NK))[i];
    __syncthreads();
    for (int c = 0; c < 10; c++) {
        int b = c * 4096 + tid * 8;
        if (b >= NB) continue;
        int idx8[8];
        #pragma unroll
        for (int t = 0; t < 8; t++) idx8[t] = g_idx[b + t];
        #pragma unroll
        for (int q = 0; q < QCH; q++) {
            const float* r = srow + q * NK;
            float4 v0 = make_float4(r[idx8[0]], r[idx8[1]], r[idx8[2]], r[idx8[3]]);
            float4 v1 = make_float4(r[idx8[4]], r[idx8[5]], r[idx8[6]], r[idx8[7]]);
            float* p = out + (size_t)(q0 + q) * NB + b;
            __stcs((float4*)p, v0);
            __stcs((float4*)(p + 4), v1);
        }
    }
}

// ======================= launch ==========================================
extern "C" void kernel_launch(void* const* d_in, const int* in_sizes, int n_in,
                              void* d_out, int out_size) {
    const float* qry = (const float*)d_in[0];   // (2048, 512)
    const float* ent = (const float*)d_in[1];   // (40000, 512)
    const float* cb  = (const float*)d_in[2];   // (2048, 512)
    float* out = (float*)d_out;                 // score | vq_loss | idx

    cudaFuncSetAttribute(k_dist, cudaFuncAttributeMaxDynamicSharedMemorySize, DIST_SMEM);
    cudaFuncSetAttribute(k_sall, cudaFuncAttributeMaxDynamicSharedMemorySize, SALL_SMEM);
    cudaFuncSetAttribute(k_gather, cudaFuncAttributeMaxDynamicSharedMemorySize, GATHER_SMEM);

    k_splitrow<<<(NB + 7) / 8, 256>>>(ent, NB, 0);
    k_splitrow<<<(NK + 7) / 8, 256>>>(cb, NK, 1);
    k_splitrow<<<(NQ + 7) / 8, 256>>>(qry, NQ, 2);
    k_flaginit<<<MAXFLAG / 256, 256>>>();
    k_dist<<<625, 256, DIST_SMEM>>>(out);
    k_repair_gemm<<<dim3(16, MAXFLAG / 128), 256>>>(ent, cb);
    k_repair_write<<<MAXFLAG / 256, 256>>>(out);
    k_sall<<<dim3(16, 32), 256, SALL_SMEM>>>();
    k_loss_final<<<1, 256>>>(out);
    k_gather<<<256, 512, GATHER_SMEM>>>(out);
}

// round 12
// speedup vs baseline: 4.7841x; 1.0140x over previous
#include <cuda_runtime.h>
#include <cuda_fp16.h>
#include <cstdint>

#define NQ 2048
#define NB 40000
#define NK 2048
#define ND 512
#define RT 64
#define MAXFLAG 16384

// ======================= device scratch (no allocation allowed) ==========
__device__ float g_c2[NK];
__device__ float g_x2[NB];
__device__ float g_bestd[NB];
__device__ int g_idx[NB];
__device__ __align__(16) float g_sall[(size_t)NQ * NK];   // 16 MB
__device__ int g_nflag;
__device__ int g_flag[MAXFLAG];
__device__ unsigned long long g_min[MAXFLAG];
__device__ __half g_eh0[(size_t)NB * ND];
__device__ __half g_eh1[(size_t)NB * ND];
__device__ __half g_ch0[(size_t)NK * ND];
__device__ __half g_ch1[(size_t)NK * ND];
__device__ __half g_qh0[(size_t)NQ * ND];
__device__ __half g_qh1[(size_t)NQ * ND];

// ======================= helpers =========================================
__device__ __forceinline__ uint32_t smem_to_u32(const void* p) {
    uint32_t a;
    asm("{ .reg .u64 t; cvta.to.shared.u64 t, %1; cvt.u32.u64 %0, t; }" : "=r"(a) : "l"(p));
    return a;
}
__device__ __forceinline__ void ldsm4(uint32_t* d, uint32_t addr) {
    asm volatile("ldmatrix.sync.aligned.m8n8.x4.shared.b16 {%0,%1,%2,%3}, [%4];"
        : "=r"(d[0]), "=r"(d[1]), "=r"(d[2]), "=r"(d[3]) : "r"(addr));
}
__device__ __forceinline__ void mma16816(float* c, const uint32_t* a, const uint32_t* b) {
    asm volatile("mma.sync.aligned.m16n8k16.row.col.f32.f16.f16.f32 "
        "{%0,%1,%2,%3}, {%4,%5,%6,%7}, {%8,%9}, {%0,%1,%2,%3};"
        : "+f"(c[0]), "+f"(c[1]), "+f"(c[2]), "+f"(c[3])
        : "r"(a[0]), "r"(a[1]), "r"(a[2]), "r"(a[3]), "r"(b[0]), "r"(b[1]));
}
__device__ __forceinline__ void cpa16(uint32_t dst, const void* src) {
    asm volatile("cp.async.cg.shared.global [%0], [%1], 16;" :: "r"(dst), "l"(src));
}
#define CPA_COMMIT() asm volatile("cp.async.commit_group;" ::: "memory")
#define CPA_WAIT1()  asm volatile("cp.async.wait_group 1;" ::: "memory")
#define CPA_WAIT0()  asm volatile("cp.async.wait_group 0;" ::: "memory")

// ======================= fused row split + norms =========================
__global__ void k_splitrow(const float* __restrict__ src, int nrows, int which) {
    int gw = (blockIdx.x * 256 + threadIdx.x) >> 5;
    int lane = threadIdx.x & 31;
    if (which == 1 && gw == 0 && lane == 0) g_nflag = 0;
    if (gw >= nrows) return;
    const float* row = src + (size_t)gw * ND;
    __half *h0, *h1;
    if (which == 0) { h0 = g_eh0; h1 = g_eh1; }
    else if (which == 1) { h0 = g_ch0; h1 = g_ch1; }
    else { h0 = g_qh0; h1 = g_qh1; }
    float s = 0.f;
    #pragma unroll
    for (int j = 0; j < 4; j++) {
        int d = lane * 4 + j * 128;
        float4 v = *(const float4*)(row + d);
        __half a0 = __float2half_rn(v.x), a1 = __float2half_rn(v.y);
        __half a2 = __float2half_rn(v.z), a3 = __float2half_rn(v.w);
        __half b0 = __float2half_rn(v.x - __half2float(a0));
        __half b1 = __float2half_rn(v.y - __half2float(a1));
        __half b2 = __float2half_rn(v.z - __half2float(a2));
        __half b3 = __float2half_rn(v.w - __half2float(a3));
        __half2* p0 = (__half2*)(h0 + (size_t)gw * ND + d);
        __half2* p1 = (__half2*)(h1 + (size_t)gw * ND + d);
        p0[0] = __halves2half2(a0, a1); p0[1] = __halves2half2(a2, a3);
        p1[0] = __halves2half2(b0, b1); p1[1] = __halves2half2(b2, b3);
        s += v.x * v.x + v.y * v.y + v.z * v.z + v.w * v.w;
    }
    #pragma unroll
    for (int o = 16; o > 0; o >>= 1) s += __shfl_xor_sync(0xffffffffu, s, o);
    if (lane == 0) {
        if (which == 0) g_x2[gw] = s;
        else if (which == 1) g_c2[gw] = s;
    }
}

__global__ void k_flaginit() {
    g_min[blockIdx.x * 256 + threadIdx.x] = 0xFFFFFFFFFFFFFFFFull;
}

// ======================= HMMA distance + fused argmin ====================
// 625 CTAs x 64 rows, 256 threads (2m x 4n warps), 3-stage cp.async, 2 CTAs/SM.
// Single __syncthreads per step: wait -> sync -> issue(s+2) -> mma.
// (valid ONLY for 3 stages: (s+2)%3 differs from s%3 and (s+1)%3)
#define STG_D 32768
#define DIST_SMEM (3 * STG_D)

__device__ __forceinline__ void issue_d(uint32_t base, size_t arow, size_t brow, int koff) {
    const int tid = threadIdx.x;
    #pragma unroll
    for (int i = 0; i < 2; i++) {
        int idx = tid + i * 256;
        int r = idx >> 3, c16 = idx & 7;
        uint32_t soff = (uint32_t)(r * 128 + ((c16 * 16) ^ ((r & 7) * 16)));
        size_t off = arow + (size_t)r * ND + koff + c16 * 8;
        cpa16(base + soff,         g_eh0 + off);
        cpa16(base + 8192u + soff, g_eh1 + off);
    }
    #pragma unroll
    for (int i = 0; i < 4; i++) {
        int idx = tid + i * 256;
        int r = idx >> 3, c16 = idx & 7;
        uint32_t soff = (uint32_t)(r * 128 + ((c16 * 16) ^ ((r & 7) * 16)));
        cpa16(base + 16384u + soff, g_ch0 + brow + (size_t)r * ND + koff + c16 * 8);
    }
}

__global__ __launch_bounds__(256, 2)
void k_dist(float* __restrict__ out) {
    extern __shared__ char smem[];
    const uint32_t sb = smem_to_u32(smem);
    const int tid = threadIdx.x;
    const int wid = tid >> 5, lane = tid & 31;
    const int warp_m = wid >> 2, warp_n = wid & 3;
    const int row0 = blockIdx.x * RT;
    const size_t arow = (size_t)row0 * ND;

    const int a_row = lane & 15;
    const int a_c0 = (lane >> 4) * 16;
    const int a_xr = (a_row & 7) * 16;
    const int b_row = (lane & 7) + ((lane >> 4) << 3);
    const int b_c0 = ((lane >> 3) & 1) * 16;
    const int b_xr = (b_row & 7) * 16;
    uint32_t a_off[2], b_off[2];
    #pragma unroll
    for (int am = 0; am < 2; am++)
        a_off[am] = (uint32_t)((warp_m * 32 + am * 16 + a_row) * 128);
    #pragma unroll
    for (int bp = 0; bp < 2; bp++)
        b_off[bp] = 16384u + (uint32_t)((warp_n * 32 + bp * 16 + b_row) * 128);

    float best[4], best2[4]; int bidx[4];
    #pragma unroll
    for (int k = 0; k < 4; k++) { best[k] = 3.4e38f; best2[k] = 3.4e38f; bidx[k] = 0; }

    issue_d(sb, arow, 0, 0); CPA_COMMIT();
    issue_d(sb + STG_D, arow, 0, 64); CPA_COMMIT();

    for (int nt = 0; nt < 16; nt++) {
        float acc[2][4][4];
        #pragma unroll
        for (int am = 0; am < 2; am++)
            #pragma unroll
            for (int an = 0; an < 4; an++)
                #pragma unroll
                for (int r = 0; r < 4; r++) acc[am][an][r] = 0.f;

        #pragma unroll
        for (int kc = 0; kc < 8; kc++) {
            const int s = nt * 8 + kc;
            if (s < 127) { CPA_WAIT1(); } else { CPA_WAIT0(); }
            __syncthreads();
            if (s + 2 < 128) {
                const int s2 = s + 2;
                issue_d(sb + (uint32_t)(s2 % 3) * STG_D,
                        arow, (size_t)((s2 >> 3) * 128) * ND, (s2 & 7) * 64);
                CPA_COMMIT();
            }
            const uint32_t base = sb + (uint32_t)(s % 3) * STG_D;
            #pragma unroll
            for (int kb = 0; kb < 4; kb++) {
                const uint32_t ca = (uint32_t)((a_c0 + kb * 32) ^ a_xr);
                const uint32_t cbo = (uint32_t)((b_c0 + kb * 32) ^ b_xr);
                uint32_t af[2][4], bf[4][2];
                #pragma unroll
                for (int bp = 0; bp < 2; bp++) {
                    uint32_t t[4];
                    ldsm4(t, base + b_off[bp] + cbo);
                    bf[bp * 2][0] = t[0]; bf[bp * 2][1] = t[1];
                    bf[bp * 2 + 1][0] = t[2]; bf[bp * 2 + 1][1] = t[3];
                }
                #pragma unroll
                for (int am = 0; am < 2; am++) ldsm4(af[am], base + a_off[am] + ca);
                #pragma unroll
                for (int am = 0; am < 2; am++)
                    #pragma unroll
                    for (int an = 0; an < 4; an++) mma16816(acc[am][an], af[am], bf[an]);
                #pragma unroll
                for (int am = 0; am < 2; am++) ldsm4(af[am], base + a_off[am] + 8192u + ca);
                #pragma unroll
                for (int am = 0; am < 2; am++)
                    #pragma unroll
                    for (int an = 0; an < 4; an++) mma16816(acc[am][an], af[am], bf[an]);
            }
        }
        // ---- per-nt epilogue ----
        #pragma unroll
        for (int am = 0; am < 2; am++) {
            #pragma unroll
            for (int an = 0; an < 4; an++) {
                int cl = warp_n * 32 + an * 8 + (lane & 3) * 2;
                float c2a = __ldg(&g_c2[nt * 128 + cl]);
                float c2b = __ldg(&g_c2[nt * 128 + cl + 1]);
                int gc = nt * 128 + cl;
                #pragma unroll
                for (int h = 0; h < 2; h++) {
                    int k = am * 2 + h;
                    float d0 = c2a - 2.f * acc[am][an][h * 2 + 0];
                    float d1 = c2b - 2.f * acc[am][an][h * 2 + 1];
                    if (d0 < best[k]) { best2[k] = best[k]; best[k] = d0; bidx[k] = gc; }
                    else if (d0 < best2[k]) best2[k] = d0;
                    if (d1 < best[k]) { best2[k] = best[k]; best[k] = d1; bidx[k] = gc + 1; }
                    else if (d1 < best2[k]) best2[k] = d1;
                }
            }
        }
    }

    // ---- final reduce: quad lanes -> smem -> per-row ----
    __syncthreads();
    float* sred1 = (float*)smem;
    float* sred2 = (float*)(smem + 1024);
    int*   sredi = (int*)(smem + 2048);
    #pragma unroll
    for (int k = 0; k < 4; k++) {
        float b1 = best[k], b2 = best2[k]; int ix = bidx[k];
        #pragma unroll
        for (int s = 1; s < 4; s <<= 1) {
            float o1 = __shfl_xor_sync(0xffffffffu, b1, s);
            float o2 = __shfl_xor_sync(0xffffffffu, b2, s);
            int oi = __shfl_xor_sync(0xffffffffu, ix, s);
            if (o1 < b1) { b2 = fminf(b1, o2); b1 = o1; ix = oi; }
            else b2 = fminf(b2, o1);
        }
        if ((lane & 3) == 0) {
            int rl = warp_m * 32 + (k >> 1) * 16 + (k & 1) * 8 + (lane >> 2);
            sred1[rl * 4 + warp_n] = b1;
            sred2[rl * 4 + warp_n] = b2;
            sredi[rl * 4 + warp_n] = ix;
        }
    }
    __syncthreads();
    if (tid < RT) {
        float b1 = sred1[tid * 4], b2 = sred2[tid * 4];
        int ix = sredi[tid * 4];
        #pragma unroll
        for (int w = 1; w < 4; w++) {
            float o1 = sred1[tid * 4 + w], o2 = sred2[tid * 4 + w];
            int oi = sredi[tid * 4 + w];
            if (o1 < b1) { b2 = fminf(b1, o2); b1 = o1; ix = oi; }
            else b2 = fminf(b2, o1);
        }
        int row = row0 + tid;
        g_idx[row] = ix;
        g_bestd[row] = b1;
        out[(size_t)NQ * NB + 1 + row] = (float)ix;
        if (b2 - b1 < 0.25f) {
            int s = atomicAdd(&g_nflag, 1);
            if (s < MAXFLAG) g_flag[s] = row;
        }
    }
}

// ======================= exact fp32 GEMM repair ==========================
__global__ __launch_bounds__(256)
void k_repair_gemm(const float* __restrict__ ent, const float* __restrict__ cb) {
    __shared__ float As[32][132];
    __shared__ float Bs[32][132];
    __shared__ int srow[128];
    int n = g_nflag;
    if (n > MAXFLAG) n = MAXFLAG;
    const int s0 = blockIdx.y * 128;
    if (s0 >= n) return;
    const int col0 = blockIdx.x * 128;
    const int tid = threadIdx.x;
    if (tid < 128) srow[tid] = (s0 + tid < n) ? g_flag[s0 + tid] : -1;
    __syncthreads();
    const int tcol = tid & 15;
    const int trow = tid >> 4;
    float acc[8][8] = {};

    for (int kk = 0; kk < ND; kk += 32) {
        #pragma unroll
        for (int it = 0; it < 4; it++) {
            int f4 = tid + it * 256;
            int r = f4 >> 3;
            int c = (f4 & 7) << 2;
            int er = srow[r];
            float4 v = make_float4(0.f, 0.f, 0.f, 0.f);
            if (er >= 0) v = *(const float4*)(ent + (size_t)er * ND + kk + c);
            As[c + 0][r] = v.x; As[c + 1][r] = v.y; As[c + 2][r] = v.z; As[c + 3][r] = v.w;
            float4 w = *(const float4*)(cb + (size_t)(col0 + r) * ND + kk + c);
            Bs[c + 0][r] = w.x; Bs[c + 1][r] = w.y; Bs[c + 2][r] = w.z; Bs[c + 3][r] = w.w;
        }
        __syncthreads();
        #pragma unroll
        for (int k = 0; k < 32; k++) {
            float4 a0 = *(const float4*)&As[k][trow * 8];
            float4 a1 = *(const float4*)&As[k][trow * 8 + 4];
            float4 b0 = *(const float4*)&Bs[k][tcol * 8];
            float4 b1 = *(const float4*)&Bs[k][tcol * 8 + 4];
            float a[8] = {a0.x, a0.y, a0.z, a0.w, a1.x, a1.y, a1.z, a1.w};
            float b[8] = {b0.x, b0.y, b0.z, b0.w, b1.x, b1.y, b1.z, b1.w};
            #pragma unroll
            for (int i = 0; i < 8; i++)
                #pragma unroll
                for (int j = 0; j < 8; j++)
                    acc[i][j] = fmaf(a[i], b[j], acc[i][j]);
        }
        __syncthreads();
    }

    #pragma unroll
    for (int i = 0; i < 8; i++) {
        int slot = s0 + trow * 8 + i;
        float best = 3.4e38f;
        int bj = 0;
        #pragma unroll
        for (int j = 0; j < 8; j++) {
            int gc = col0 + tcol * 8 + j;
            float d = g_c2[gc] - 2.0f * acc[i][j];
            if (d < best) { best = d; bj = gc; }
        }
        unsigned int kb = __float_as_uint(best);
        kb = (kb & 0x80000000u) ? ~kb : (kb | 0x80000000u);
        unsigned long long pack = ((unsigned long long)kb << 32) | (unsigned int)bj;
        #pragma unroll
        for (int s = 1; s < 16; s <<= 1) {
            unsigned long long o = __shfl_xor_sync(0xffffffffu, pack, s);
            pack = (o < pack) ? o : pack;
        }
        if (tcol == 0 && slot < n) atomicMin(&g_min[slot], pack);
    }
}

__global__ void k_repair_write(float* __restrict__ out) {
    int s = blockIdx.x * 256 + threadIdx.x;
    int n = g_nflag;
    if (n > MAXFLAG) n = MAXFLAG;
    if (s >= n) return;
    unsigned long long w = g_min[s];
    int j = (int)(unsigned int)(w & 0xFFFFFFFFull);
    unsigned int kb = (unsigned int)(w >> 32);
    unsigned int fb = (kb & 0x80000000u) ? (kb & 0x7FFFFFFFu) : ~kb;
    int b = g_flag[s];
    g_idx[b] = j;
    g_bestd[b] = __uint_as_float(fb);
    out[(size_t)NQ * NB + 1 + b] = (float)j;
}

// ======================= S_all = query @ codebook^T (3-product HMMA) =====
// 2-stage buffer -> R9 double-sync, 1-ahead prefetch (correct for 2 stages).
#define STG_S 49152
#define SALL_SMEM (2 * STG_S)

__device__ __forceinline__ void issue_s(uint32_t base, size_t arow, size_t brow, int koff) {
    const int tid = threadIdx.x;
    #pragma unroll
    for (int i = 0; i < 2; i++) {
        int idx = tid + i * 256;
        int r = idx >> 3, c16 = idx & 7;
        uint32_t soff = (uint32_t)(r * 128 + ((c16 * 16) ^ ((r & 7) * 16)));
        size_t off = arow + (size_t)r * ND + koff + c16 * 8;
        cpa16(base + soff,         g_qh0 + off);
        cpa16(base + 8192u + soff, g_qh1 + off);
    }
    #pragma unroll
    for (int i = 0; i < 4; i++) {
        int idx = tid + i * 256;
        int r = idx >> 3, c16 = idx & 7;
        uint32_t soff = (uint32_t)(r * 128 + ((c16 * 16) ^ ((r & 7) * 16)));
        size_t off = brow + (size_t)r * ND + koff + c16 * 8;
        cpa16(base + 16384u + soff, g_ch0 + off);
        cpa16(base + 32768u + soff, g_ch1 + off);
    }
}

__global__ __launch_bounds__(256, 2)
void k_sall() {
    extern __shared__ char smem[];
    const uint32_t sb = smem_to_u32(smem);
    const int tid = threadIdx.x;
    const int wid = tid >> 5, lane = tid & 31;
    const int warp_m = wid >> 2, warp_n = wid & 3;
    const int col0 = blockIdx.x * 128;
    const int row0 = blockIdx.y * RT;
    const size_t arow = (size_t)row0 * ND;
    const size_t brow = (size_t)col0 * ND;

    const int a_row = lane & 15;
    const int a_c0 = (lane >> 4) * 16;
    const int a_xr = (a_row & 7) * 16;
    const int b_row = (lane & 7) + ((lane >> 4) << 3);
    const int b_c0 = ((lane >> 3) & 1) * 16;
    const int b_xr = (b_row & 7) * 16;
    uint32_t a_off[2], b_off[2];
    #pragma unroll
    for (int am = 0; am < 2; am++)
        a_off[am] = (uint32_t)((warp_m * 32 + am * 16 + a_row) * 128);
    #pragma unroll
    for (int bp = 0; bp < 2; bp++)
        b_off[bp] = 16384u + (uint32_t)((warp_n * 32 + bp * 16 + b_row) * 128);

    float acc[2][4][4];
    #pragma unroll
    for (int am = 0; am < 2; am++)
        #pragma unroll
        for (int an = 0; an < 4; an++)
            #pragma unroll
            for (int r = 0; r < 4; r++) acc[am][an][r] = 0.f;

    issue_s(sb, arow, brow, 0); CPA_COMMIT();

    #pragma unroll
    for (int s = 0; s < 8; s++) {
        if (s < 7) {
            issue_s(sb + (uint32_t)((s + 1) & 1) * STG_S, arow, brow, (s + 1) * 64);
            CPA_COMMIT();
            CPA_WAIT1();
        } else {
            CPA_WAIT0();
        }
        __syncthreads();
        const uint32_t base = sb + (uint32_t)(s & 1) * STG_S;
        #pragma unroll
        for (int kb = 0; kb < 4; kb++) {
            const uint32_t ca = (uint32_t)((a_c0 + kb * 32) ^ a_xr);
            const uint32_t cbo = (uint32_t)((b_c0 + kb * 32) ^ b_xr);
            uint32_t af[2][4], bf[4][2], bg[4][2];
            #pragma unroll
            for (int bp = 0; bp < 2; bp++) {
                uint32_t t[4];
                ldsm4(t, base + b_off[bp] + cbo);
                bf[bp * 2][0] = t[0]; bf[bp * 2][1] = t[1];
                bf[bp * 2 + 1][0] = t[2]; bf[bp * 2 + 1][1] = t[3];
            }
            #pragma unroll
            for (int bp = 0; bp < 2; bp++) {
                uint32_t t[4];
                ldsm4(t, base + b_off[bp] + 16384u + cbo);
                bg[bp * 2][0] = t[0]; bg[bp * 2][1] = t[1];
                bg[bp * 2 + 1][0] = t[2]; bg[bp * 2 + 1][1] = t[3];
            }
            #pragma unroll
            for (int am = 0; am < 2; am++) ldsm4(af[am], base + a_off[am] + ca);
            #pragma unroll
            for (int am = 0; am < 2; am++)
                #pragma unroll
                for (int an = 0; an < 4; an++) mma16816(acc[am][an], af[am], bf[an]);
            #pragma unroll
            for (int am = 0; am < 2; am++)
                #pragma unroll
                for (int an = 0; an < 4; an++) mma16816(acc[am][an], af[am], bg[an]);
            #pragma unroll
            for (int am = 0; am < 2; am++) ldsm4(af[am], base + a_off[am] + 8192u + ca);
            #pragma unroll
            for (int am = 0; am < 2; am++)
                #pragma unroll
                for (int an = 0; an < 4; an++) mma16816(acc[am][an], af[am], bf[an]);
        }
        __syncthreads();
    }

    #pragma unroll
    for (int am = 0; am < 2; am++)
        #pragma unroll
        for (int h = 0; h < 2; h++) {
            int r = row0 + warp_m * 32 + am * 16 + h * 8 + (lane >> 2);
            #pragma unroll
            for (int an = 0; an < 4; an++) {
                int c = col0 + warp_n * 32 + an * 8 + (lane & 3) * 2;
                *(float2*)(g_sall + (size_t)r * NK + c) =
                    make_float2(acc[am][an][h * 2], acc[am][an][h * 2 + 1]);
            }
        }
}

// ======================= vq_loss: mean(x2 + bestd) * 1.25 ================
__global__ void k_loss_final(float* __restrict__ out) {
    __shared__ double sred[256];
    const int tid = threadIdx.x;
    double s = 0.0;
    for (int b = tid; b < NB; b += 256) s += (double)g_x2[b] + (double)g_bestd[b];
    sred[tid] = s;
    __syncthreads();
    for (int o = 128; o > 0; o >>= 1) {
        if (tid < o) sred[tid] += sred[tid + o];
        __syncthreads();
    }
    if (tid == 0) out[(size_t)NQ * NB] = (float)(1.25 * sred[0] / ((double)NB * (double)ND));
}

// ======================= score gather ====================================
#define QCH 8
#define GATHER_SMEM (QCH * NK * 4)
__global__ __launch_bounds__(512)
void k_gather(float* __restrict__ out) {
    extern __shared__ float srow[];   // [QCH][NK]
    const int tid = threadIdx.x;
    const int q0 = blockIdx.x * QCH;
    for (int i = tid; i < QCH * NK / 4; i += 512)
        ((float4*)srow)[i] = ((const float4*)(g_sall + (size_t)q0 * NK))[i];
    __syncthreads();
    for (int c = 0; c < 10; c++) {
        int b = c * 4096 + tid * 8;
        if (b >= NB) continue;
        int idx8[8];
        #pragma unroll
        for (int t = 0; t < 8; t++) idx8[t] = g_idx[b + t];
        #pragma unroll
        for (int q = 0; q < QCH; q++) {
            const float* r = srow + q * NK;
            float4 v0 = make_float4(r[idx8[0]], r[idx8[1]], r[idx8[2]], r[idx8[3]]);
            float4 v1 = make_float4(r[idx8[4]], r[idx8[5]], r[idx8[6]], r[idx8[7]]);
            float* p = out + (size_t)(q0 + q) * NB + b;
            __stcs((float4*)p, v0);
            __stcs((float4*)(p + 4), v1);
        }
    }
}

// ======================= launch ==========================================
extern "C" void kernel_launch(void* const* d_in, const int* in_sizes, int n_in,
                              void* d_out, int out_size) {
    const float* qry = (const float*)d_in[0];   // (2048, 512)
    const float* ent = (const float*)d_in[1];   // (40000, 512)
    const float* cb  = (const float*)d_in[2];   // (2048, 512)
    float* out = (float*)d_out;                 // score | vq_loss | idx

    cudaFuncSetAttribute(k_dist, cudaFuncAttributeMaxDynamicSharedMemorySize, DIST_SMEM);
    cudaFuncSetAttribute(k_sall, cudaFuncAttributeMaxDynamicSharedMemorySize, SALL_SMEM);
    cudaFuncSetAttribute(k_gather, cudaFuncAttributeMaxDynamicSharedMemorySize, GATHER_SMEM);

    k_splitrow<<<(NB + 7) / 8, 256>>>(ent, NB, 0);
    k_splitrow<<<(NK + 7) / 8, 256>>>(cb, NK, 1);
    k_splitrow<<<(NQ + 7) / 8, 256>>>(qry, NQ, 2);
    k_flaginit<<<MAXFLAG / 256, 256>>>();
    k_dist<<<625, 256, DIST_SMEM>>>(out);
    k_repair_gemm<<<dim3(16, MAXFLAG / 128), 256>>>(ent, cb);
    k_repair_write<<<MAXFLAG / 256, 256>>>(out);
    k_sall<<<dim3(16, 32), 256, SALL_SMEM>>>();
    k_loss_final<<<1, 256>>>(out);
    k_gather<<<256, 512, GATHER_SMEM>>>(out);
}

// round 13
// speedup vs baseline: 5.0231x; 1.0500x over previous
#include <cuda_runtime.h>
#include <cuda_fp16.h>
#include <cstdint>

#define NQ 2048
#define NB 40000
#define NK 2048
#define ND 512
#define RT 64
#define MAXFLAG 16384

// ======================= device scratch (no allocation allowed) ==========
__device__ float g_c2[NK];
__device__ float g_x2[NB];
__device__ float g_bestd[NB];
__device__ int g_idx[NB];
__device__ __align__(16) float g_sall[(size_t)NQ * NK];   // 16 MB
__device__ int g_nflag;
__device__ int g_flag[MAXFLAG];
__device__ unsigned long long g_min[MAXFLAG];
__device__ __half g_eh0[(size_t)NB * ND];
__device__ __half g_eh1[(size_t)NB * ND];
__device__ __half g_ch0[(size_t)NK * ND];
__device__ __half g_ch1[(size_t)NK * ND];
__device__ __half g_qh0[(size_t)NQ * ND];
__device__ __half g_qh1[(size_t)NQ * ND];

// ======================= helpers =========================================
__device__ __forceinline__ uint32_t smem_to_u32(const void* p) {
    uint32_t a;
    asm("{ .reg .u64 t; cvta.to.shared.u64 t, %1; cvt.u32.u64 %0, t; }" : "=r"(a) : "l"(p));
    return a;
}
__device__ __forceinline__ void ldsm4(uint32_t* d, uint32_t addr) {
    asm volatile("ldmatrix.sync.aligned.m8n8.x4.shared.b16 {%0,%1,%2,%3}, [%4];"
        : "=r"(d[0]), "=r"(d[1]), "=r"(d[2]), "=r"(d[3]) : "r"(addr));
}
__device__ __forceinline__ void mma16816(float* c, const uint32_t* a, const uint32_t* b) {
    asm volatile("mma.sync.aligned.m16n8k16.row.col.f32.f16.f16.f32 "
        "{%0,%1,%2,%3}, {%4,%5,%6,%7}, {%8,%9}, {%0,%1,%2,%3};"
        : "+f"(c[0]), "+f"(c[1]), "+f"(c[2]), "+f"(c[3])
        : "r"(a[0]), "r"(a[1]), "r"(a[2]), "r"(a[3]), "r"(b[0]), "r"(b[1]));
}
__device__ __forceinline__ void cpa16(uint32_t dst, const void* src) {
    asm volatile("cp.async.cg.shared.global [%0], [%1], 16;" :: "r"(dst), "l"(src));
}
#define CPA_COMMIT() asm volatile("cp.async.commit_group;" ::: "memory")
#define CPA_WAIT1()  asm volatile("cp.async.wait_group 1;" ::: "memory")
#define CPA_WAIT0()  asm volatile("cp.async.wait_group 0;" ::: "memory")

// ======================= fused row split + norms =========================
__global__ void k_splitrow(const float* __restrict__ src, int nrows, int which) {
    int gw = (blockIdx.x * 256 + threadIdx.x) >> 5;
    int lane = threadIdx.x & 31;
    if (which == 1 && gw == 0 && lane == 0) g_nflag = 0;
    if (gw >= nrows) return;
    const float* row = src + (size_t)gw * ND;
    __half *h0, *h1;
    if (which == 0) { h0 = g_eh0; h1 = g_eh1; }
    else if (which == 1) { h0 = g_ch0; h1 = g_ch1; }
    else { h0 = g_qh0; h1 = g_qh1; }
    float s = 0.f;
    #pragma unroll
    for (int j = 0; j < 4; j++) {
        int d = lane * 4 + j * 128;
        float4 v = *(const float4*)(row + d);
        __half a0 = __float2half_rn(v.x), a1 = __float2half_rn(v.y);
        __half a2 = __float2half_rn(v.z), a3 = __float2half_rn(v.w);
        __half b0 = __float2half_rn(v.x - __half2float(a0));
        __half b1 = __float2half_rn(v.y - __half2float(a1));
        __half b2 = __float2half_rn(v.z - __half2float(a2));
        __half b3 = __float2half_rn(v.w - __half2float(a3));
        __half2* p0 = (__half2*)(h0 + (size_t)gw * ND + d);
        __half2* p1 = (__half2*)(h1 + (size_t)gw * ND + d);
        p0[0] = __halves2half2(a0, a1); p0[1] = __halves2half2(a2, a3);
        p1[0] = __halves2half2(b0, b1); p1[1] = __halves2half2(b2, b3);
        s += v.x * v.x + v.y * v.y + v.z * v.z + v.w * v.w;
    }
    #pragma unroll
    for (int o = 16; o > 0; o >>= 1) s += __shfl_xor_sync(0xffffffffu, s, o);
    if (lane == 0) {
        if (which == 0) g_x2[gw] = s;
        else if (which == 1) g_c2[gw] = s;
    }
}

__global__ void k_flaginit() {
    g_min[blockIdx.x * 256 + threadIdx.x] = 0xFFFFFFFFFFFFFFFFull;
}

// ======================= HMMA distance + fused argmin ====================
// 625 CTAs x 64 rows, 256 threads (2m x 4n warps), 2-stage cp.async,
// 3 CTAs/SM (64KB smem/CTA, 24 warps/SM). Double-sync per step (2-stage!).
// 2-product emulation: (A0+A1)*B0 = x . fp16(c); GEMM repair covers flags.
#define STG_D 32768
#define DIST_SMEM (2 * STG_D)

__device__ __forceinline__ void issue_d(uint32_t base, size_t arow, size_t brow, int koff) {
    const int tid = threadIdx.x;
    #pragma unroll
    for (int i = 0; i < 2; i++) {
        int idx = tid + i * 256;
        int r = idx >> 3, c16 = idx & 7;
        uint32_t soff = (uint32_t)(r * 128 + ((c16 * 16) ^ ((r & 7) * 16)));
        size_t off = arow + (size_t)r * ND + koff + c16 * 8;
        cpa16(base + soff,         g_eh0 + off);
        cpa16(base + 8192u + soff, g_eh1 + off);
    }
    #pragma unroll
    for (int i = 0; i < 4; i++) {
        int idx = tid + i * 256;
        int r = idx >> 3, c16 = idx & 7;
        uint32_t soff = (uint32_t)(r * 128 + ((c16 * 16) ^ ((r & 7) * 16)));
        cpa16(base + 16384u + soff, g_ch0 + brow + (size_t)r * ND + koff + c16 * 8);
    }
}

__global__ __launch_bounds__(256, 3)
void k_dist(float* __restrict__ out) {
    extern __shared__ char smem[];
    const uint32_t sb = smem_to_u32(smem);
    const int tid = threadIdx.x;
    const int wid = tid >> 5, lane = tid & 31;
    const int warp_m = wid >> 2, warp_n = wid & 3;
    const int row0 = blockIdx.x * RT;
    const size_t arow = (size_t)row0 * ND;

    const int a_row = lane & 15;
    const int a_c0 = (lane >> 4) * 16;
    const int a_xr = (a_row & 7) * 16;
    const int b_row = (lane & 7) + ((lane >> 4) << 3);
    const int b_c0 = ((lane >> 3) & 1) * 16;
    const int b_xr = (b_row & 7) * 16;
    uint32_t a_off[2], b_off[2];
    #pragma unroll
    for (int am = 0; am < 2; am++)
        a_off[am] = (uint32_t)((warp_m * 32 + am * 16 + a_row) * 128);
    #pragma unroll
    for (int bp = 0; bp < 2; bp++)
        b_off[bp] = 16384u + (uint32_t)((warp_n * 32 + bp * 16 + b_row) * 128);

    float best[4], best2[4]; int bidx[4];
    #pragma unroll
    for (int k = 0; k < 4; k++) { best[k] = 3.4e38f; best2[k] = 3.4e38f; bidx[k] = 0; }

    issue_d(sb, arow, 0, 0); CPA_COMMIT();

    for (int nt = 0; nt < 16; nt++) {
        float acc[2][4][4];
        #pragma unroll
        for (int am = 0; am < 2; am++)
            #pragma unroll
            for (int an = 0; an < 4; an++)
                #pragma unroll
                for (int r = 0; r < 4; r++) acc[am][an][r] = 0.f;

        #pragma unroll
        for (int kc = 0; kc < 8; kc++) {
            const int s = nt * 8 + kc;
            if (s < 127) {
                const int s1 = s + 1;
                // buffer (s+1)&1 was released by the trailing sync of step s-1
                issue_d(sb + (uint32_t)(s1 & 1) * STG_D,
                        arow, (size_t)((s1 >> 3) * 128) * ND, (s1 & 7) * 64);
                CPA_COMMIT();
                CPA_WAIT1();
            } else {
                CPA_WAIT0();
            }
            __syncthreads();
            const uint32_t base = sb + (uint32_t)(s & 1) * STG_D;
            #pragma unroll
            for (int kb = 0; kb < 4; kb++) {
                const uint32_t ca = (uint32_t)((a_c0 + kb * 32) ^ a_xr);
                const uint32_t cbo = (uint32_t)((b_c0 + kb * 32) ^ b_xr);
                uint32_t af[2][4], bf[4][2];
                #pragma unroll
                for (int bp = 0; bp < 2; bp++) {
                    uint32_t t[4];
                    ldsm4(t, base + b_off[bp] + cbo);
                    bf[bp * 2][0] = t[0]; bf[bp * 2][1] = t[1];
                    bf[bp * 2 + 1][0] = t[2]; bf[bp * 2 + 1][1] = t[3];
                }
                #pragma unroll
                for (int am = 0; am < 2; am++) ldsm4(af[am], base + a_off[am] + ca);
                #pragma unroll
                for (int am = 0; am < 2; am++)
                    #pragma unroll
                    for (int an = 0; an < 4; an++) mma16816(acc[am][an], af[am], bf[an]);
                #pragma unroll
                for (int am = 0; am < 2; am++) ldsm4(af[am], base + a_off[am] + 8192u + ca);
                #pragma unroll
                for (int am = 0; am < 2; am++)
                    #pragma unroll
                    for (int an = 0; an < 4; an++) mma16816(acc[am][an], af[am], bf[an]);
            }
            __syncthreads();   // release buffer s&1 for issue at step s+1
        }
        // ---- per-nt epilogue (registers + __ldg only) ----
        #pragma unroll
        for (int am = 0; am < 2; am++) {
            #pragma unroll
            for (int an = 0; an < 4; an++) {
                int cl = warp_n * 32 + an * 8 + (lane & 3) * 2;
                float c2a = __ldg(&g_c2[nt * 128 + cl]);
                float c2b = __ldg(&g_c2[nt * 128 + cl + 1]);
                int gc = nt * 128 + cl;
                #pragma unroll
                for (int h = 0; h < 2; h++) {
                    int k = am * 2 + h;
                    float d0 = c2a - 2.f * acc[am][an][h * 2 + 0];
                    float d1 = c2b - 2.f * acc[am][an][h * 2 + 1];
                    if (d0 < best[k]) { best2[k] = best[k]; best[k] = d0; bidx[k] = gc; }
                    else if (d0 < best2[k]) best2[k] = d0;
                    if (d1 < best[k]) { best2[k] = best[k]; best[k] = d1; bidx[k] = gc + 1; }
                    else if (d1 < best2[k]) best2[k] = d1;
                }
            }
        }
    }

    // ---- final reduce: quad lanes -> smem -> per-row ----
    __syncthreads();
    float* sred1 = (float*)smem;
    float* sred2 = (float*)(smem + 1024);
    int*   sredi = (int*)(smem + 2048);
    #pragma unroll
    for (int k = 0; k < 4; k++) {
        float b1 = best[k], b2 = best2[k]; int ix = bidx[k];
        #pragma unroll
        for (int s = 1; s < 4; s <<= 1) {
            float o1 = __shfl_xor_sync(0xffffffffu, b1, s);
            float o2 = __shfl_xor_sync(0xffffffffu, b2, s);
            int oi = __shfl_xor_sync(0xffffffffu, ix, s);
            if (o1 < b1) { b2 = fminf(b1, o2); b1 = o1; ix = oi; }
            else b2 = fminf(b2, o1);
        }
        if ((lane & 3) == 0) {
            int rl = warp_m * 32 + (k >> 1) * 16 + (k & 1) * 8 + (lane >> 2);
            sred1[rl * 4 + warp_n] = b1;
            sred2[rl * 4 + warp_n] = b2;
            sredi[rl * 4 + warp_n] = ix;
        }
    }
    __syncthreads();
    if (tid < RT) {
        float b1 = sred1[tid * 4], b2 = sred2[tid * 4];
        int ix = sredi[tid * 4];
        #pragma unroll
        for (int w = 1; w < 4; w++) {
            float o1 = sred1[tid * 4 + w], o2 = sred2[tid * 4 + w];
            int oi = sredi[tid * 4 + w];
            if (o1 < b1) { b2 = fminf(b1, o2); b1 = o1; ix = oi; }
            else b2 = fminf(b2, o1);
        }
        int row = row0 + tid;
        g_idx[row] = ix;
        g_bestd[row] = b1;
        out[(size_t)NQ * NB + 1 + row] = (float)ix;
        if (b2 - b1 < 0.25f) {
            int s = atomicAdd(&g_nflag, 1);
            if (s < MAXFLAG) g_flag[s] = row;
        }
    }
}

// ======================= exact fp32 GEMM repair ==========================
__global__ __launch_bounds__(256)
void k_repair_gemm(const float* __restrict__ ent, const float* __restrict__ cb) {
    __shared__ float As[32][132];
    __shared__ float Bs[32][132];
    __shared__ int srow[128];
    int n = g_nflag;
    if (n > MAXFLAG) n = MAXFLAG;
    const int s0 = blockIdx.y * 128;
    if (s0 >= n) return;
    const int col0 = blockIdx.x * 128;
    const int tid = threadIdx.x;
    if (tid < 128) srow[tid] = (s0 + tid < n) ? g_flag[s0 + tid] : -1;
    __syncthreads();
    const int tcol = tid & 15;
    const int trow = tid >> 4;
    float acc[8][8] = {};

    for (int kk = 0; kk < ND; kk += 32) {
        #pragma unroll
        for (int it = 0; it < 4; it++) {
            int f4 = tid + it * 256;
            int r = f4 >> 3;
            int c = (f4 & 7) << 2;
            int er = srow[r];
            float4 v = make_float4(0.f, 0.f, 0.f, 0.f);
            if (er >= 0) v = *(const float4*)(ent + (size_t)er * ND + kk + c);
            As[c + 0][r] = v.x; As[c + 1][r] = v.y; As[c + 2][r] = v.z; As[c + 3][r] = v.w;
            float4 w = *(const float4*)(cb + (size_t)(col0 + r) * ND + kk + c);
            Bs[c + 0][r] = w.x; Bs[c + 1][r] = w.y; Bs[c + 2][r] = w.z; Bs[c + 3][r] = w.w;
        }
        __syncthreads();
        #pragma unroll
        for (int k = 0; k < 32; k++) {
            float4 a0 = *(const float4*)&As[k][trow * 8];
            float4 a1 = *(const float4*)&As[k][trow * 8 + 4];
            float4 b0 = *(const float4*)&Bs[k][tcol * 8];
            float4 b1 = *(const float4*)&Bs[k][tcol * 8 + 4];
            float a[8] = {a0.x, a0.y, a0.z, a0.w, a1.x, a1.y, a1.z, a1.w};
            float b[8] = {b0.x, b0.y, b0.z, b0.w, b1.x, b1.y, b1.z, b1.w};
            #pragma unroll
            for (int i = 0; i < 8; i++)
                #pragma unroll
                for (int j = 0; j < 8; j++)
                    acc[i][j] = fmaf(a[i], b[j], acc[i][j]);
        }
        __syncthreads();
    }

    #pragma unroll
    for (int i = 0; i < 8; i++) {
        int slot = s0 + trow * 8 + i;
        float best = 3.4e38f;
        int bj = 0;
        #pragma unroll
        for (int j = 0; j < 8; j++) {
            int gc = col0 + tcol * 8 + j;
            float d = g_c2[gc] - 2.0f * acc[i][j];
            if (d < best) { best = d; bj = gc; }
        }
        unsigned int kb = __float_as_uint(best);
        kb = (kb & 0x80000000u) ? ~kb : (kb | 0x80000000u);
        unsigned long long pack = ((unsigned long long)kb << 32) | (unsigned int)bj;
        #pragma unroll
        for (int s = 1; s < 16; s <<= 1) {
            unsigned long long o = __shfl_xor_sync(0xffffffffu, pack, s);
            pack = (o < pack) ? o : pack;
        }
        if (tcol == 0 && slot < n) atomicMin(&g_min[slot], pack);
    }
}

__global__ void k_repair_write(float* __restrict__ out) {
    int s = blockIdx.x * 256 + threadIdx.x;
    int n = g_nflag;
    if (n > MAXFLAG) n = MAXFLAG;
    if (s >= n) return;
    unsigned long long w = g_min[s];
    int j = (int)(unsigned int)(w & 0xFFFFFFFFull);
    unsigned int kb = (unsigned int)(w >> 32);
    unsigned int fb = (kb & 0x80000000u) ? (kb & 0x7FFFFFFFu) : ~kb;
    int b = g_flag[s];
    g_idx[b] = j;
    g_bestd[b] = __uint_as_float(fb);
    out[(size_t)NQ * NB + 1 + b] = (float)j;
}

// ======================= S_all = query @ codebook^T (2-product HMMA) =====
// q = q0 + q1, c ~ fp16(c): S ~ (q0+q1).c0. Dropped q.(c - fp16(c)) term has
// sigma ~0.007 abs on score magnitude ~23 -> rel err ~3e-4 < 1e-3 threshold.
// 3-stage 32KB pipeline, single sync per step, 2 CTAs/SM.
#define STG_S 32768
#define SALL_SMEM (3 * STG_S)

__device__ __forceinline__ void issue_s(uint32_t base, size_t arow, size_t brow, int koff) {
    const int tid = threadIdx.x;
    #pragma unroll
    for (int i = 0; i < 2; i++) {
        int idx = tid + i * 256;
        int r = idx >> 3, c16 = idx & 7;
        uint32_t soff = (uint32_t)(r * 128 + ((c16 * 16) ^ ((r & 7) * 16)));
        size_t off = arow + (size_t)r * ND + koff + c16 * 8;
        cpa16(base + soff,         g_qh0 + off);
        cpa16(base + 8192u + soff, g_qh1 + off);
    }
    #pragma unroll
    for (int i = 0; i < 4; i++) {
        int idx = tid + i * 256;
        int r = idx >> 3, c16 = idx & 7;
        uint32_t soff = (uint32_t)(r * 128 + ((c16 * 16) ^ ((r & 7) * 16)));
        cpa16(base + 16384u + soff, g_ch0 + brow + (size_t)r * ND + koff + c16 * 8);
    }
}

__global__ __launch_bounds__(256, 2)
void k_sall() {
    extern __shared__ char smem[];
    const uint32_t sb = smem_to_u32(smem);
    const int tid = threadIdx.x;
    const int wid = tid >> 5, lane = tid & 31;
    const int warp_m = wid >> 2, warp_n = wid & 3;
    const int col0 = blockIdx.x * 128;
    const int row0 = blockIdx.y * RT;
    const size_t arow = (size_t)row0 * ND;
    const size_t brow = (size_t)col0 * ND;

    const int a_row = lane & 15;
    const int a_c0 = (lane >> 4) * 16;
    const int a_xr = (a_row & 7) * 16;
    const int b_row = (lane & 7) + ((lane >> 4) << 3);
    const int b_c0 = ((lane >> 3) & 1) * 16;
    const int b_xr = (b_row & 7) * 16;
    uint32_t a_off[2], b_off[2];
    #pragma unroll
    for (int am = 0; am < 2; am++)
        a_off[am] = (uint32_t)((warp_m * 32 + am * 16 + a_row) * 128);
    #pragma unroll
    for (int bp = 0; bp < 2; bp++)
        b_off[bp] = 16384u + (uint32_t)((warp_n * 32 + bp * 16 + b_row) * 128);

    float acc[2][4][4];
    #pragma unroll
    for (int am = 0; am < 2; am++)
        #pragma unroll
        for (int an = 0; an < 4; an++)
            #pragma unroll
            for (int r = 0; r < 4; r++) acc[am][an][r] = 0.f;

    issue_s(sb, arow, brow, 0); CPA_COMMIT();
    issue_s(sb + STG_S, arow, brow, 64); CPA_COMMIT();

    #pragma unroll
    for (int s = 0; s < 8; s++) {
        if (s < 7) { CPA_WAIT1(); } else { CPA_WAIT0(); }
        __syncthreads();
        if (s + 2 < 8) {
            issue_s(sb + (uint32_t)((s + 2) % 3) * STG_S, arow, brow, (s + 2) * 64);
            CPA_COMMIT();
        }
        const uint32_t base = sb + (uint32_t)(s % 3) * STG_S;
        #pragma unroll
        for (int kb = 0; kb < 4; kb++) {
            const uint32_t ca = (uint32_t)((a_c0 + kb * 32) ^ a_xr);
            const uint32_t cbo = (uint32_t)((b_c0 + kb * 32) ^ b_xr);
            uint32_t af[2][4], bf[4][2];
            #pragma unroll
            for (int bp = 0; bp < 2; bp++) {
                uint32_t t[4];
                ldsm4(t, base + b_off[bp] + cbo);
                bf[bp * 2][0] = t[0]; bf[bp * 2][1] = t[1];
                bf[bp * 2 + 1][0] = t[2]; bf[bp * 2 + 1][1] = t[3];
            }
            #pragma unroll
            for (int am = 0; am < 2; am++) ldsm4(af[am], base + a_off[am] + ca);
            #pragma unroll
            for (int am = 0; am < 2; am++)
                #pragma unroll
                for (int an = 0; an < 4; an++) mma16816(acc[am][an], af[am], bf[an]);
            #pragma unroll
            for (int am = 0; am < 2; am++) ldsm4(af[am], base + a_off[am] + 8192u + ca);
            #pragma unroll
            for (int am = 0; am < 2; am++)
                #pragma unroll
                for (int an = 0; an < 4; an++) mma16816(acc[am][an], af[am], bf[an]);
        }
    }

    #pragma unroll
    for (int am = 0; am < 2; am++)
        #pragma unroll
        for (int h = 0; h < 2; h++) {
            int r = row0 + warp_m * 32 + am * 16 + h * 8 + (lane >> 2);
            #pragma unroll
            for (int an = 0; an < 4; an++) {
                int c = col0 + warp_n * 32 + an * 8 + (lane & 3) * 2;
                *(float2*)(g_sall + (size_t)r * NK + c) =
                    make_float2(acc[am][an][h * 2], acc[am][an][h * 2 + 1]);
            }
        }
}

// ======================= vq_loss: mean(x2 + bestd) * 1.25 ================
__global__ void k_loss_final(float* __restrict__ out) {
    __shared__ double sred[256];
    const int tid = threadIdx.x;
    double s = 0.0;
    for (int b = tid; b < NB; b += 256) s += (double)g_x2[b] + (double)g_bestd[b];
    sred[tid] = s;
    __syncthreads();
    for (int o = 128; o > 0; o >>= 1) {
        if (tid < o) sred[tid] += sred[tid + o];
        __syncthreads();
    }
    if (tid == 0) out[(size_t)NQ * NB] = (float)(1.25 * sred[0] / ((double)NB * (double)ND));
}

// ======================= score gather ====================================
#define QCH 4
#define GATHER_SMEM (QCH * NK * 4)
__global__ __launch_bounds__(512)
void k_gather(float* __restrict__ out) {
    extern __shared__ float srow[];   // [QCH][NK]
    const int tid = threadIdx.x;
    const int q0 = blockIdx.x * QCH;
    for (int i = tid; i < QCH * NK / 4; i += 512)
        ((float4*)srow)[i] = ((const float4*)(g_sall + (size_t)q0 * NK))[i];
    __syncthreads();
    for (int c = 0; c < 10; c++) {
        int b = c * 4096 + tid * 8;
        if (b >= NB) continue;
        int idx8[8];
        #pragma unroll
        for (int t = 0; t < 8; t++) idx8[t] = g_idx[b + t];
        #pragma unroll
        for (int q = 0; q < QCH; q++) {
            const float* r = srow + q * NK;
            float4 v0 = make_float4(r[idx8[0]], r[idx8[1]], r[idx8[2]], r[idx8[3]]);
            float4 v1 = make_float4(r[idx8[4]], r[idx8[5]], r[idx8[6]], r[idx8[7]]);
            float* p = out + (size_t)(q0 + q) * NB + b;
            __stcs((float4*)p, v0);
            __stcs((float4*)(p + 4), v1);
        }
    }
}

// ======================= launch ==========================================
extern "C" void kernel_launch(void* const* d_in, const int* in_sizes, int n_in,
                              void* d_out, int out_size) {
    const float* qry = (const float*)d_in[0];   // (2048, 512)
    const float* ent = (const float*)d_in[1];   // (40000, 512)
    const float* cb  = (const float*)d_in[2];   // (2048, 512)
    float* out = (float*)d_out;                 // score | vq_loss | idx

    cudaFuncSetAttribute(k_dist, cudaFuncAttributeMaxDynamicSharedMemorySize, DIST_SMEM);
    cudaFuncSetAttribute(k_sall, cudaFuncAttributeMaxDynamicSharedMemorySize, SALL_SMEM);
    cudaFuncSetAttribute(k_gather, cudaFuncAttributeMaxDynamicSharedMemorySize, GATHER_SMEM);

    k_splitrow<<<(NB + 7) / 8, 256>>>(ent, NB, 0);
    k_splitrow<<<(NK + 7) / 8, 256>>>(cb, NK, 1);
    k_splitrow<<<(NQ + 7) / 8, 256>>>(qry, NQ, 2);
    k_flaginit<<<MAXFLAG / 256, 256>>>();
    k_dist<<<625, 256, DIST_SMEM>>>(out);
    k_repair_gemm<<<dim3(16, MAXFLAG / 128), 256>>>(ent, cb);
    k_repair_write<<<MAXFLAG / 256, 256>>>(out);
    k_sall<<<dim3(16, 32), 256, SALL_SMEM>>>();
    k_loss_final<<<1, 256>>>(out);
    k_gather<<<512, 512, GATHER_SMEM>>>(out);
}

// round 14
// speedup vs baseline: 6.6416x; 1.3222x over previous
#include <cuda_runtime.h>
#include <cuda_fp16.h>
#include <cstdint>

#define NQ 2048
#define NB 40000
#define NK 2048
#define ND 512
#define RT 64
#define MAXFLAG 16384

// ======================= device scratch (no allocation allowed) ==========
__device__ float g_c2[NK];
__device__ float g_x2[NB];
__device__ float g_bestd[NB];
__device__ int g_idx[NB];
__device__ __align__(16) float g_sall[(size_t)NQ * NK];   // 16 MB
__device__ int g_nflag;
__device__ int g_flag[MAXFLAG];
__device__ unsigned long long g_min[MAXFLAG];
__device__ __half g_eh0[(size_t)NB * ND];
__device__ __half g_ch0[(size_t)NK * ND];
__device__ __half g_qh0[(size_t)NQ * ND];

// ======================= helpers =========================================
__device__ __forceinline__ uint32_t smem_to_u32(const void* p) {
    uint32_t a;
    asm("{ .reg .u64 t; cvta.to.shared.u64 t, %1; cvt.u32.u64 %0, t; }" : "=r"(a) : "l"(p));
    return a;
}
__device__ __forceinline__ void ldsm4(uint32_t* d, uint32_t addr) {
    asm volatile("ldmatrix.sync.aligned.m8n8.x4.shared.b16 {%0,%1,%2,%3}, [%4];"
        : "=r"(d[0]), "=r"(d[1]), "=r"(d[2]), "=r"(d[3]) : "r"(addr));
}
__device__ __forceinline__ void mma16816(float* c, const uint32_t* a, const uint32_t* b) {
    asm volatile("mma.sync.aligned.m16n8k16.row.col.f32.f16.f16.f32 "
        "{%0,%1,%2,%3}, {%4,%5,%6,%7}, {%8,%9}, {%0,%1,%2,%3};"
        : "+f"(c[0]), "+f"(c[1]), "+f"(c[2]), "+f"(c[3])
        : "r"(a[0]), "r"(a[1]), "r"(a[2]), "r"(a[3]), "r"(b[0]), "r"(b[1]));
}
__device__ __forceinline__ void cpa16(uint32_t dst, const void* src) {
    asm volatile("cp.async.cg.shared.global [%0], [%1], 16;" :: "r"(dst), "l"(src));
}
#define CPA_COMMIT() asm volatile("cp.async.commit_group;" ::: "memory")
#define CPA_WAIT1()  asm volatile("cp.async.wait_group 1;" ::: "memory")
#define CPA_WAIT0()  asm volatile("cp.async.wait_group 0;" ::: "memory")

// ======================= fp16 row cast + norms ===========================
// warp per row: h0 = fp16(x); norms for entity (x2) and codebook (c2).
__global__ void k_splitrow(const float* __restrict__ src, int nrows, int which) {
    int gw = (blockIdx.x * 256 + threadIdx.x) >> 5;
    int lane = threadIdx.x & 31;
    if (which == 1 && gw == 0 && lane == 0) g_nflag = 0;
    if (gw >= nrows) return;
    const float* row = src + (size_t)gw * ND;
    __half* h0 = (which == 0) ? g_eh0 : (which == 1) ? g_ch0 : g_qh0;
    float s = 0.f;
    #pragma unroll
    for (int j = 0; j < 4; j++) {
        int d = lane * 4 + j * 128;
        float4 v = *(const float4*)(row + d);
        __half a0 = __float2half_rn(v.x), a1 = __float2half_rn(v.y);
        __half a2 = __float2half_rn(v.z), a3 = __float2half_rn(v.w);
        __half2* p0 = (__half2*)(h0 + (size_t)gw * ND + d);
        p0[0] = __halves2half2(a0, a1); p0[1] = __halves2half2(a2, a3);
        s += v.x * v.x + v.y * v.y + v.z * v.z + v.w * v.w;
    }
    #pragma unroll
    for (int o = 16; o > 0; o >>= 1) s += __shfl_xor_sync(0xffffffffu, s, o);
    if (lane == 0) {
        if (which == 0) g_x2[gw] = s;
        else if (which == 1) g_c2[gw] = s;
    }
}

__global__ void k_flaginit() {
    g_min[blockIdx.x * 256 + threadIdx.x] = 0xFFFFFFFFFFFFFFFFull;
}

// ======================= HMMA distance + fused argmin ====================
// 625 CTAs x 64 rows, 256 threads (2m x 4n warps), 3-stage 24KB cp.async,
// 3 CTAs/SM (72KB smem/CTA). Single sync per step (3-stage safe).
// Single-product emulation: fp16(x) . fp16(c); sigma ~0.018 << flag thr 0.25.
#define STG_D 24576
#define DIST_SMEM (3 * STG_D)

__device__ __forceinline__ void issue_d(uint32_t base, size_t arow, size_t brow, int koff) {
    const int tid = threadIdx.x;
    #pragma unroll
    for (int i = 0; i < 2; i++) {          // A0: 64 x 64 half = 8KB
        int idx = tid + i * 256;
        int r = idx >> 3, c16 = idx & 7;
        uint32_t soff = (uint32_t)(r * 128 + ((c16 * 16) ^ ((r & 7) * 16)));
        cpa16(base + soff, g_eh0 + arow + (size_t)r * ND + koff + c16 * 8);
    }
    #pragma unroll
    for (int i = 0; i < 4; i++) {          // B0: 128 x 64 half = 16KB
        int idx = tid + i * 256;
        int r = idx >> 3, c16 = idx & 7;
        uint32_t soff = (uint32_t)(r * 128 + ((c16 * 16) ^ ((r & 7) * 16)));
        cpa16(base + 8192u + soff, g_ch0 + brow + (size_t)r * ND + koff + c16 * 8);
    }
}

__global__ __launch_bounds__(256, 3)
void k_dist(float* __restrict__ out) {
    extern __shared__ char smem[];
    const uint32_t sb = smem_to_u32(smem);
    const int tid = threadIdx.x;
    const int wid = tid >> 5, lane = tid & 31;
    const int warp_m = wid >> 2, warp_n = wid & 3;
    const int row0 = blockIdx.x * RT;
    const size_t arow = (size_t)row0 * ND;

    const int a_row = lane & 15;
    const int a_c0 = (lane >> 4) * 16;
    const int a_xr = (a_row & 7) * 16;
    const int b_row = (lane & 7) + ((lane >> 4) << 3);
    const int b_c0 = ((lane >> 3) & 1) * 16;
    const int b_xr = (b_row & 7) * 16;
    uint32_t a_off[2], b_off[2];
    #pragma unroll
    for (int am = 0; am < 2; am++)
        a_off[am] = (uint32_t)((warp_m * 32 + am * 16 + a_row) * 128);
    #pragma unroll
    for (int bp = 0; bp < 2; bp++)
        b_off[bp] = 8192u + (uint32_t)((warp_n * 32 + bp * 16 + b_row) * 128);

    float best[4], best2[4]; int bidx[4];
    #pragma unroll
    for (int k = 0; k < 4; k++) { best[k] = 3.4e38f; best2[k] = 3.4e38f; bidx[k] = 0; }

    issue_d(sb, arow, 0, 0); CPA_COMMIT();
    issue_d(sb + STG_D, arow, 0, 64); CPA_COMMIT();

    for (int nt = 0; nt < 16; nt++) {
        float acc[2][4][4];
        #pragma unroll
        for (int am = 0; am < 2; am++)
            #pragma unroll
            for (int an = 0; an < 4; an++)
                #pragma unroll
                for (int r = 0; r < 4; r++) acc[am][an][r] = 0.f;

        #pragma unroll
        for (int kc = 0; kc < 8; kc++) {
            const int s = nt * 8 + kc;
            if (s < 127) { CPA_WAIT1(); } else { CPA_WAIT0(); }
            __syncthreads();
            if (s + 2 < 128) {
                const int s2 = s + 2;
                issue_d(sb + (uint32_t)(s2 % 3) * STG_D,
                        arow, (size_t)((s2 >> 3) * 128) * ND, (s2 & 7) * 64);
                CPA_COMMIT();
            }
            const uint32_t base = sb + (uint32_t)(s % 3) * STG_D;
            #pragma unroll
            for (int kb = 0; kb < 4; kb++) {
                const uint32_t ca = (uint32_t)((a_c0 + kb * 32) ^ a_xr);
                const uint32_t cbo = (uint32_t)((b_c0 + kb * 32) ^ b_xr);
                uint32_t af[2][4], bf[4][2];
                #pragma unroll
                for (int bp = 0; bp < 2; bp++) {
                    uint32_t t[4];
                    ldsm4(t, base + b_off[bp] + cbo);
                    bf[bp * 2][0] = t[0]; bf[bp * 2][1] = t[1];
                    bf[bp * 2 + 1][0] = t[2]; bf[bp * 2 + 1][1] = t[3];
                }
                #pragma unroll
                for (int am = 0; am < 2; am++) ldsm4(af[am], base + a_off[am] + ca);
                #pragma unroll
                for (int am = 0; am < 2; am++)
                    #pragma unroll
                    for (int an = 0; an < 4; an++) mma16816(acc[am][an], af[am], bf[an]);
            }
        }
        // ---- per-nt epilogue ----
        #pragma unroll
        for (int am = 0; am < 2; am++) {
            #pragma unroll
            for (int an = 0; an < 4; an++) {
                int cl = warp_n * 32 + an * 8 + (lane & 3) * 2;
                float c2a = __ldg(&g_c2[nt * 128 + cl]);
                float c2b = __ldg(&g_c2[nt * 128 + cl + 1]);
                int gc = nt * 128 + cl;
                #pragma unroll
                for (int h = 0; h < 2; h++) {
                    int k = am * 2 + h;
                    float d0 = c2a - 2.f * acc[am][an][h * 2 + 0];
                    float d1 = c2b - 2.f * acc[am][an][h * 2 + 1];
                    if (d0 < best[k]) { best2[k] = best[k]; best[k] = d0; bidx[k] = gc; }
                    else if (d0 < best2[k]) best2[k] = d0;
                    if (d1 < best[k]) { best2[k] = best[k]; best[k] = d1; bidx[k] = gc + 1; }
                    else if (d1 < best2[k]) best2[k] = d1;
                }
            }
        }
    }

    // ---- final reduce: quad lanes -> smem -> per-row ----
    __syncthreads();
    float* sred1 = (float*)smem;
    float* sred2 = (float*)(smem + 1024);
    int*   sredi = (int*)(smem + 2048);
    #pragma unroll
    for (int k = 0; k < 4; k++) {
        float b1 = best[k], b2 = best2[k]; int ix = bidx[k];
        #pragma unroll
        for (int s = 1; s < 4; s <<= 1) {
            float o1 = __shfl_xor_sync(0xffffffffu, b1, s);
            float o2 = __shfl_xor_sync(0xffffffffu, b2, s);
            int oi = __shfl_xor_sync(0xffffffffu, ix, s);
            if (o1 < b1) { b2 = fminf(b1, o2); b1 = o1; ix = oi; }
            else b2 = fminf(b2, o1);
        }
        if ((lane & 3) == 0) {
            int rl = warp_m * 32 + (k >> 1) * 16 + (k & 1) * 8 + (lane >> 2);
            sred1[rl * 4 + warp_n] = b1;
            sred2[rl * 4 + warp_n] = b2;
            sredi[rl * 4 + warp_n] = ix;
        }
    }
    __syncthreads();
    if (tid < RT) {
        float b1 = sred1[tid * 4], b2 = sred2[tid * 4];
        int ix = sredi[tid * 4];
        #pragma unroll
        for (int w = 1; w < 4; w++) {
            float o1 = sred1[tid * 4 + w], o2 = sred2[tid * 4 + w];
            int oi = sredi[tid * 4 + w];
            if (o1 < b1) { b2 = fminf(b1, o2); b1 = o1; ix = oi; }
            else b2 = fminf(b2, o1);
        }
        int row = row0 + tid;
        g_idx[row] = ix;
        g_bestd[row] = b1;
        out[(size_t)NQ * NB + 1 + row] = (float)ix;
        if (b2 - b1 < 0.25f) {
            int s = atomicAdd(&g_nflag, 1);
            if (s < MAXFLAG) g_flag[s] = row;
        }
    }
}

// ======================= exact fp32 GEMM repair ==========================
__global__ __launch_bounds__(256)
void k_repair_gemm(const float* __restrict__ ent, const float* __restrict__ cb) {
    __shared__ float As[32][132];
    __shared__ float Bs[32][132];
    __shared__ int srow[128];
    int n = g_nflag;
    if (n > MAXFLAG) n = MAXFLAG;
    const int s0 = blockIdx.y * 128;
    if (s0 >= n) return;
    const int col0 = blockIdx.x * 128;
    const int tid = threadIdx.x;
    if (tid < 128) srow[tid] = (s0 + tid < n) ? g_flag[s0 + tid] : -1;
    __syncthreads();
    const int tcol = tid & 15;
    const int trow = tid >> 4;
    float acc[8][8] = {};

    for (int kk = 0; kk < ND; kk += 32) {
        #pragma unroll
        for (int it = 0; it < 4; it++) {
            int f4 = tid + it * 256;
            int r = f4 >> 3;
            int c = (f4 & 7) << 2;
            int er = srow[r];
            float4 v = make_float4(0.f, 0.f, 0.f, 0.f);
            if (er >= 0) v = *(const float4*)(ent + (size_t)er * ND + kk + c);
            As[c + 0][r] = v.x; As[c + 1][r] = v.y; As[c + 2][r] = v.z; As[c + 3][r] = v.w;
            float4 w = *(const float4*)(cb + (size_t)(col0 + r) * ND + kk + c);
            Bs[c + 0][r] = w.x; Bs[c + 1][r] = w.y; Bs[c + 2][r] = w.z; Bs[c + 3][r] = w.w;
        }
        __syncthreads();
        #pragma unroll
        for (int k = 0; k < 32; k++) {
            float4 a0 = *(const float4*)&As[k][trow * 8];
            float4 a1 = *(const float4*)&As[k][trow * 8 + 4];
            float4 b0 = *(const float4*)&Bs[k][tcol * 8];
            float4 b1 = *(const float4*)&Bs[k][tcol * 8 + 4];
            float a[8] = {a0.x, a0.y, a0.z, a0.w, a1.x, a1.y, a1.z, a1.w};
            float b[8] = {b0.x, b0.y, b0.z, b0.w, b1.x, b1.y, b1.z, b1.w};
            #pragma unroll
            for (int i = 0; i < 8; i++)
                #pragma unroll
                for (int j = 0; j < 8; j++)
                    acc[i][j] = fmaf(a[i], b[j], acc[i][j]);
        }
        __syncthreads();
    }

    #pragma unroll
    for (int i = 0; i < 8; i++) {
        int slot = s0 + trow * 8 + i;
        float best = 3.4e38f;
        int bj = 0;
        #pragma unroll
        for (int j = 0; j < 8; j++) {
            int gc = col0 + tcol * 8 + j;
            float d = g_c2[gc] - 2.0f * acc[i][j];
            if (d < best) { best = d; bj = gc; }
        }
        unsigned int kb = __float_as_uint(best);
        kb = (kb & 0x80000000u) ? ~kb : (kb | 0x80000000u);
        unsigned long long pack = ((unsigned long long)kb << 32) | (unsigned int)bj;
        #pragma unroll
        for (int s = 1; s < 16; s <<= 1) {
            unsigned long long o = __shfl_xor_sync(0xffffffffu, pack, s);
            pack = (o < pack) ? o : pack;
        }
        if (tcol == 0 && slot < n) atomicMin(&g_min[slot], pack);
    }
}

__global__ void k_repair_write(float* __restrict__ out) {
    int s = blockIdx.x * 256 + threadIdx.x;
    int n = g_nflag;
    if (n > MAXFLAG) n = MAXFLAG;
    if (s >= n) return;
    unsigned long long w = g_min[s];
    int j = (int)(unsigned int)(w & 0xFFFFFFFFull);
    unsigned int kb = (unsigned int)(w >> 32);
    unsigned int fb = (kb & 0x80000000u) ? (kb & 0x7FFFFFFFu) : ~kb;
    int b = g_flag[s];
    g_idx[b] = j;
    g_bestd[b] = __uint_as_float(fb);
    out[(size_t)NQ * NB + 1 + b] = (float)j;
}

// ======================= S_all = query @ codebook^T (1-product HMMA) =====
// S ~ fp16(q) . fp16(c): score rel err ~3e-4 < 1e-3 threshold.
#define STG_S 24576
#define SALL_SMEM (3 * STG_S)

__device__ __forceinline__ void issue_s(uint32_t base, size_t arow, size_t brow, int koff) {
    const int tid = threadIdx.x;
    #pragma unroll
    for (int i = 0; i < 2; i++) {
        int idx = tid + i * 256;
        int r = idx >> 3, c16 = idx & 7;
        uint32_t soff = (uint32_t)(r * 128 + ((c16 * 16) ^ ((r & 7) * 16)));
        cpa16(base + soff, g_qh0 + arow + (size_t)r * ND + koff + c16 * 8);
    }
    #pragma unroll
    for (int i = 0; i < 4; i++) {
        int idx = tid + i * 256;
        int r = idx >> 3, c16 = idx & 7;
        uint32_t soff = (uint32_t)(r * 128 + ((c16 * 16) ^ ((r & 7) * 16)));
        cpa16(base + 8192u + soff, g_ch0 + brow + (size_t)r * ND + koff + c16 * 8);
    }
}

__global__ __launch_bounds__(256, 3)
void k_sall() {
    extern __shared__ char smem[];
    const uint32_t sb = smem_to_u32(smem);
    const int tid = threadIdx.x;
    const int wid = tid >> 5, lane = tid & 31;
    const int warp_m = wid >> 2, warp_n = wid & 3;
    const int col0 = blockIdx.x * 128;
    const int row0 = blockIdx.y * RT;
    const size_t arow = (size_t)row0 * ND;
    const size_t brow = (size_t)col0 * ND;

    const int a_row = lane & 15;
    const int a_c0 = (lane >> 4) * 16;
    const int a_xr = (a_row & 7) * 16;
    const int b_row = (lane & 7) + ((lane >> 4) << 3);
    const int b_c0 = ((lane >> 3) & 1) * 16;
    const int b_xr = (b_row & 7) * 16;
    uint32_t a_off[2], b_off[2];
    #pragma unroll
    for (int am = 0; am < 2; am++)
        a_off[am] = (uint32_t)((warp_m * 32 + am * 16 + a_row) * 128);
    #pragma unroll
    for (int bp = 0; bp < 2; bp++)
        b_off[bp] = 8192u + (uint32_t)((warp_n * 32 + bp * 16 + b_row) * 128);

    float acc[2][4][4];
    #pragma unroll
    for (int am = 0; am < 2; am++)
        #pragma unroll
        for (int an = 0; an < 4; an++)
            #pragma unroll
            for (int r = 0; r < 4; r++) acc[am][an][r] = 0.f;

    issue_s(sb, arow, brow, 0); CPA_COMMIT();
    issue_s(sb + STG_S, arow, brow, 64); CPA_COMMIT();

    #pragma unroll
    for (int s = 0; s < 8; s++) {
        if (s < 7) { CPA_WAIT1(); } else { CPA_WAIT0(); }
        __syncthreads();
        if (s + 2 < 8) {
            issue_s(sb + (uint32_t)((s + 2) % 3) * STG_S, arow, brow, (s + 2) * 64);
            CPA_COMMIT();
        }
        const uint32_t base = sb + (uint32_t)(s % 3) * STG_S;
        #pragma unroll
        for (int kb = 0; kb < 4; kb++) {
            const uint32_t ca = (uint32_t)((a_c0 + kb * 32) ^ a_xr);
            const uint32_t cbo = (uint32_t)((b_c0 + kb * 32) ^ b_xr);
            uint32_t af[2][4], bf[4][2];
            #pragma unroll
            for (int bp = 0; bp < 2; bp++) {
                uint32_t t[4];
                ldsm4(t, base + b_off[bp] + cbo);
                bf[bp * 2][0] = t[0]; bf[bp * 2][1] = t[1];
                bf[bp * 2 + 1][0] = t[2]; bf[bp * 2 + 1][1] = t[3];
            }
            #pragma unroll
            for (int am = 0; am < 2; am++) ldsm4(af[am], base + a_off[am] + ca);
            #pragma unroll
            for (int am = 0; am < 2; am++)
                #pragma unroll
                for (int an = 0; an < 4; an++) mma16816(acc[am][an], af[am], bf[an]);
        }
    }

    #pragma unroll
    for (int am = 0; am < 2; am++)
        #pragma unroll
        for (int h = 0; h < 2; h++) {
            int r = row0 + warp_m * 32 + am * 16 + h * 8 + (lane >> 2);
            #pragma unroll
            for (int an = 0; an < 4; an++) {
                int c = col0 + warp_n * 32 + an * 8 + (lane & 3) * 2;
                *(float2*)(g_sall + (size_t)r * NK + c) =
                    make_float2(acc[am][an][h * 2], acc[am][an][h * 2 + 1]);
            }
        }
}

// ======================= vq_loss: mean(x2 + bestd) * 1.25 ================
__global__ void k_loss_final(float* __restrict__ out) {
    __shared__ double sred[256];
    const int tid = threadIdx.x;
    double s = 0.0;
    for (int b = tid; b < NB; b += 256) s += (double)g_x2[b] + (double)g_bestd[b];
    sred[tid] = s;
    __syncthreads();
    for (int o = 128; o > 0; o >>= 1) {
        if (tid < o) sred[tid] += sred[tid + o];
        __syncthreads();
    }
    if (tid == 0) out[(size_t)NQ * NB] = (float)(1.25 * sred[0] / ((double)NB * (double)ND));
}

// ======================= score gather ====================================
#define QCH 4
#define GATHER_SMEM (QCH * NK * 4)
__global__ __launch_bounds__(512)
void k_gather(float* __restrict__ out) {
    extern __shared__ float srow[];   // [QCH][NK]
    const int tid = threadIdx.x;
    const int q0 = blockIdx.x * QCH;
    for (int i = tid; i < QCH * NK / 4; i += 512)
        ((float4*)srow)[i] = ((const float4*)(g_sall + (size_t)q0 * NK))[i];
    __syncthreads();
    for (int c = 0; c < 10; c++) {
        int b = c * 4096 + tid * 8;
        if (b >= NB) continue;
        int idx8[8];
        #pragma unroll
        for (int t = 0; t < 8; t++) idx8[t] = g_idx[b + t];
        #pragma unroll
        for (int q = 0; q < QCH; q++) {
            const float* r = srow + q * NK;
            float4 v0 = make_float4(r[idx8[0]], r[idx8[1]], r[idx8[2]], r[idx8[3]]);
            float4 v1 = make_float4(r[idx8[4]], r[idx8[5]], r[idx8[6]], r[idx8[7]]);
            float* p = out + (size_t)(q0 + q) * NB + b;
            __stcs((float4*)p, v0);
            __stcs((float4*)(p + 4), v1);
        }
    }
}

// ======================= launch ==========================================
extern "C" void kernel_launch(void* const* d_in, const int* in_sizes, int n_in,
                              void* d_out, int out_size) {
    const float* qry = (const float*)d_in[0];   // (2048, 512)
    const float* ent = (const float*)d_in[1];   // (40000, 512)
    const float* cb  = (const float*)d_in[2];   // (2048, 512)
    float* out = (float*)d_out;                 // score | vq_loss | idx

    cudaFuncSetAttribute(k_dist, cudaFuncAttributeMaxDynamicSharedMemorySize, DIST_SMEM);
    cudaFuncSetAttribute(k_sall, cudaFuncAttributeMaxDynamicSharedMemorySize, SALL_SMEM);
    cudaFuncSetAttribute(k_gather, cudaFuncAttributeMaxDynamicSharedMemorySize, GATHER_SMEM);

    k_splitrow<<<(NB + 7) / 8, 256>>>(ent, NB, 0);
    k_splitrow<<<(NK + 7) / 8, 256>>>(cb, NK, 1);
    k_splitrow<<<(NQ + 7) / 8, 256>>>(qry, NQ, 2);
    k_flaginit<<<MAXFLAG / 256, 256>>>();
    k_dist<<<625, 256, DIST_SMEM>>>(out);
    k_repair_gemm<<<dim3(16, MAXFLAG / 128), 256>>>(ent, cb);
    k_repair_write<<<MAXFLAG / 256, 256>>>(out);
    k_sall<<<dim3(16, 32), 256, SALL_SMEM>>>();
    k_loss_final<<<1, 256>>>(out);
    k_gather<<<512, 512, GATHER_SMEM>>>(out);
}